// round 1
// baseline (speedup 1.0000x reference)
#include <cuda_runtime.h>
#include <math.h>

#define B_  8
#define S_  1024
#define D_  1024
#define H_  16
#define DK  64
#define BH  (B_ * H_)        // 128
#define MROWS (B_ * S_)      // 8192

// Scratch (no allocations allowed): projections, context, and attn fallback.
__device__ float g_q[(size_t)B_ * H_ * S_ * DK];
__device__ float g_k[(size_t)B_ * H_ * S_ * DK];
__device__ float g_v[(size_t)B_ * H_ * S_ * DK];
__device__ float g_ctx[(size_t)B_ * H_ * S_ * DK];
__device__ float g_attn[(size_t)B_ * H_ * S_ * S_];   // 536 MB, used only if attn not in d_out

// ---------------------------------------------------------------------------
// Projection: out[b,h,s,j] = sum_d X[b,s,d] * W[h,d,j] + bias[h,j]
// grid = (H_, MROWS/64), block = 256
// ---------------------------------------------------------------------------
__global__ __launch_bounds__(256) void proj_kernel(
    const float* __restrict__ X,      // [MROWS, D_]
    const float* __restrict__ W,      // [H_, D_, DK]
    const float* __restrict__ bias,   // [H_, DK]
    float* __restrict__ out)          // [B_, H_, S_, DK]
{
    const int h  = blockIdx.x;
    const int m0 = blockIdx.y * 64;
    __shared__ float As[32][68];   // transposed A tile: As[k][m]
    __shared__ float Bs[32][68];   // B tile: Bs[k][n]
    const int tid = threadIdx.x;
    const int tx = tid & 15, ty = tid >> 4;
    float acc[4][4] = {};
    const float* Wh = W + (size_t)h * D_ * DK;

    for (int k0 = 0; k0 < D_; k0 += 32) {
        #pragma unroll
        for (int i = 0; i < 8; i++) {                 // A: 64 rows x 32 k
            int idx = tid + i * 256;
            int r = idx >> 5, kk = idx & 31;
            As[kk][r] = X[(size_t)(m0 + r) * D_ + k0 + kk];
        }
        #pragma unroll
        for (int i = 0; i < 8; i++) {                 // B: 32 k x 64 n
            int idx = tid + i * 256;
            int kk = idx >> 6, c = idx & 63;
            Bs[kk][c] = Wh[(k0 + kk) * DK + c];
        }
        __syncthreads();
        #pragma unroll
        for (int kk = 0; kk < 32; kk++) {
            float4 av = *(const float4*)&As[kk][ty * 4];
            float4 bv = *(const float4*)&Bs[kk][tx * 4];
            float a4[4] = {av.x, av.y, av.z, av.w};
            float b4[4] = {bv.x, bv.y, bv.z, bv.w};
            #pragma unroll
            for (int i = 0; i < 4; i++)
                #pragma unroll
                for (int j = 0; j < 4; j++)
                    acc[i][j] += a4[i] * b4[j];
        }
        __syncthreads();
    }
    #pragma unroll
    for (int i = 0; i < 4; i++) {
        int m = m0 + ty * 4 + i;
        int b = m >> 10, s = m & 1023;
        float* orow = out + (((size_t)(b * H_ + h)) * S_ + s) * DK + tx * 4;
        #pragma unroll
        for (int j = 0; j < 4; j++)
            orow[j] = acc[i][j] + bias[h * DK + tx * 4 + j];
    }
}

// ---------------------------------------------------------------------------
// Scores: attn[bh,s,t] = (q[bh,s,:] . k[bh,t,:]) / 8
// grid = (S_/64, S_/64, BH), block = 256
// ---------------------------------------------------------------------------
__global__ __launch_bounds__(256) void scores_kernel(
    const float* __restrict__ q, const float* __restrict__ k,
    float* __restrict__ attn)
{
    const int bh = blockIdx.z;
    const int t0 = blockIdx.x * 64;
    const int s0 = blockIdx.y * 64;
    const float* qb = q + (size_t)bh * S_ * DK;
    const float* kb = k + (size_t)bh * S_ * DK;
    __shared__ float As[32][68];
    __shared__ float Bs[32][68];
    const int tid = threadIdx.x;
    const int tx = tid & 15, ty = tid >> 4;
    float acc[4][4] = {};

    for (int k0 = 0; k0 < DK; k0 += 32) {
        #pragma unroll
        for (int i = 0; i < 8; i++) {
            int idx = tid + i * 256;
            int r = idx >> 5, kk = idx & 31;
            As[kk][r] = qb[(s0 + r) * DK + k0 + kk];
            Bs[kk][r] = kb[(t0 + r) * DK + k0 + kk];
        }
        __syncthreads();
        #pragma unroll
        for (int kk = 0; kk < 32; kk++) {
            float4 av = *(const float4*)&As[kk][ty * 4];
            float4 bv = *(const float4*)&Bs[kk][tx * 4];
            float a4[4] = {av.x, av.y, av.z, av.w};
            float b4[4] = {bv.x, bv.y, bv.z, bv.w};
            #pragma unroll
            for (int i = 0; i < 4; i++)
                #pragma unroll
                for (int j = 0; j < 4; j++)
                    acc[i][j] += a4[i] * b4[j];
        }
        __syncthreads();
    }
    #pragma unroll
    for (int i = 0; i < 4; i++) {
        int s = s0 + ty * 4 + i;
        float* row = attn + ((size_t)bh * S_ + s) * S_ + t0 + tx * 4;
        #pragma unroll
        for (int j = 0; j < 4; j++)
            row[j] = acc[i][j] * 0.125f;   // 1/sqrt(64)
    }
}

// ---------------------------------------------------------------------------
// Row softmax in place. grid = BH*S_, block = 256 (each thread: 4 elems)
// ---------------------------------------------------------------------------
__global__ __launch_bounds__(256) void softmax_kernel(float* __restrict__ attn)
{
    const size_t row = blockIdx.x;
    float* p = attn + row * S_;
    const int tid = threadIdx.x;
    float4 v = ((float4*)p)[tid];

    __shared__ float red[256];
    float m = fmaxf(fmaxf(v.x, v.y), fmaxf(v.z, v.w));
    red[tid] = m;
    __syncthreads();
    #pragma unroll
    for (int off = 128; off > 0; off >>= 1) {
        if (tid < off) red[tid] = fmaxf(red[tid], red[tid + off]);
        __syncthreads();
    }
    const float mx = red[0];
    __syncthreads();

    float e0 = expf(v.x - mx), e1 = expf(v.y - mx);
    float e2 = expf(v.z - mx), e3 = expf(v.w - mx);
    red[tid] = (e0 + e1) + (e2 + e3);
    __syncthreads();
    #pragma unroll
    for (int off = 128; off > 0; off >>= 1) {
        if (tid < off) red[tid] += red[tid + off];
        __syncthreads();
    }
    const float inv = 1.0f / red[0];
    float4 o = make_float4(e0 * inv, e1 * inv, e2 * inv, e3 * inv);
    ((float4*)p)[tid] = o;
}

// ---------------------------------------------------------------------------
// Context: ctx[bh,s,j] = sum_t attn[bh,s,t] * v[bh,t,j]
// grid = (S_/64, BH), block = 256
// ---------------------------------------------------------------------------
__global__ __launch_bounds__(256) void ctx_kernel(
    const float* __restrict__ attn, const float* __restrict__ v,
    float* __restrict__ ctx)
{
    const int bh = blockIdx.y;
    const int s0 = blockIdx.x * 64;
    const float* ab = attn + (size_t)bh * S_ * S_;
    const float* vb = v + (size_t)bh * S_ * DK;
    __shared__ float As[32][68];
    __shared__ float Bs[32][68];
    const int tid = threadIdx.x;
    const int tx = tid & 15, ty = tid >> 4;
    float acc[4][4] = {};

    for (int k0 = 0; k0 < S_; k0 += 32) {
        #pragma unroll
        for (int i = 0; i < 8; i++) {
            int idx = tid + i * 256;
            int r = idx >> 5, kk = idx & 31;
            As[kk][r] = ab[(s0 + r) * S_ + k0 + kk];
        }
        #pragma unroll
        for (int i = 0; i < 8; i++) {
            int idx = tid + i * 256;
            int kk = idx >> 6, c = idx & 63;
            Bs[kk][c] = vb[(k0 + kk) * DK + c];
        }
        __syncthreads();
        #pragma unroll
        for (int kk = 0; kk < 32; kk++) {
            float4 av = *(const float4*)&As[kk][ty * 4];
            float4 bv = *(const float4*)&Bs[kk][tx * 4];
            float a4[4] = {av.x, av.y, av.z, av.w};
            float b4[4] = {bv.x, bv.y, bv.z, bv.w};
            #pragma unroll
            for (int i = 0; i < 4; i++)
                #pragma unroll
                for (int j = 0; j < 4; j++)
                    acc[i][j] += a4[i] * b4[j];
        }
        __syncthreads();
    }
    #pragma unroll
    for (int i = 0; i < 4; i++) {
        int s = s0 + ty * 4 + i;
        float* orow = ctx + ((size_t)bh * S_ + s) * DK + tx * 4;
        #pragma unroll
        for (int j = 0; j < 4; j++)
            orow[j] = acc[i][j];
    }
}

// ---------------------------------------------------------------------------
// Output projection: out[b,s,n] = sum_{h,j} ctx[b,h,s,j] * Wo[h*64+j, n] + bo[n]
// grid = (D_/64, MROWS/64), block = 256
// ---------------------------------------------------------------------------
__global__ __launch_bounds__(256) void outproj_kernel(
    const float* __restrict__ ctx, const float* __restrict__ Wo,
    const float* __restrict__ bo, float* __restrict__ out)
{
    const int n0 = blockIdx.x * 64;
    const int m0 = blockIdx.y * 64;
    __shared__ float As[32][68];
    __shared__ float Bs[32][68];
    const int tid = threadIdx.x;
    const int tx = tid & 15, ty = tid >> 4;
    float acc[4][4] = {};

    for (int k0 = 0; k0 < H_ * DK; k0 += 32) {
        #pragma unroll
        for (int i = 0; i < 8; i++) {
            int idx = tid + i * 256;
            int r = idx >> 5, kk = idx & 31;
            int m = m0 + r;
            int b = m >> 10, s = m & 1023;
            int kg = k0 + kk;
            int h = kg >> 6, j = kg & 63;
            As[kk][r] = ctx[(((size_t)b * H_ + h) * S_ + s) * DK + j];
        }
        #pragma unroll
        for (int i = 0; i < 8; i++) {
            int idx = tid + i * 256;
            int kk = idx >> 6, c = idx & 63;
            Bs[kk][c] = Wo[(size_t)(k0 + kk) * D_ + n0 + c];
        }
        __syncthreads();
        #pragma unroll
        for (int kk = 0; kk < 32; kk++) {
            float4 av = *(const float4*)&As[kk][ty * 4];
            float4 bv = *(const float4*)&Bs[kk][tx * 4];
            float a4[4] = {av.x, av.y, av.z, av.w};
            float b4[4] = {bv.x, bv.y, bv.z, bv.w};
            #pragma unroll
            for (int i = 0; i < 4; i++)
                #pragma unroll
                for (int j = 0; j < 4; j++)
                    acc[i][j] += a4[i] * b4[j];
        }
        __syncthreads();
    }
    #pragma unroll
    for (int i = 0; i < 4; i++) {
        int m = m0 + ty * 4 + i;
        float* orow = out + (size_t)m * D_ + n0 + tx * 4;
        #pragma unroll
        for (int j = 0; j < 4; j++)
            orow[j] = acc[i][j] + bo[n0 + tx * 4 + j];
    }
}

// ---------------------------------------------------------------------------
extern "C" void kernel_launch(void* const* d_in, const int* in_sizes, int n_in,
                              void* d_out, int out_size)
{
    const float* query = (const float*)d_in[0];
    const float* key   = (const float*)d_in[1];
    const float* value = (const float*)d_in[2];
    const float* Wq    = (const float*)d_in[3];
    const float* bq    = (const float*)d_in[4];
    const float* Wk    = (const float*)d_in[5];
    const float* bk    = (const float*)d_in[6];
    const float* Wv    = (const float*)d_in[7];
    const float* bv    = (const float*)d_in[8];
    const float* Wo    = (const float*)d_in[9];
    const float* bo    = (const float*)d_in[10];
    float* out = (float*)d_out;

    float *qp, *kp, *vp, *cp, *attn_scratch;
    cudaGetSymbolAddress((void**)&qp, g_q);
    cudaGetSymbolAddress((void**)&kp, g_k);
    cudaGetSymbolAddress((void**)&vp, g_v);
    cudaGetSymbolAddress((void**)&cp, g_ctx);
    cudaGetSymbolAddress((void**)&attn_scratch, g_attn);

    const size_t out_elems  = (size_t)B_ * S_ * D_;          // 8,388,608
    const size_t attn_elems = (size_t)B_ * H_ * S_ * S_;     // 134,217,728
    float* attn = ((size_t)out_size >= out_elems + attn_elems)
                      ? (out + out_elems)     // (output, attn) packed in d_out
                      : attn_scratch;

    dim3 blk(256);
    proj_kernel<<<dim3(H_, MROWS / 64), blk>>>(query, Wq, bq, qp);
    proj_kernel<<<dim3(H_, MROWS / 64), blk>>>(key,   Wk, bk, kp);
    proj_kernel<<<dim3(H_, MROWS / 64), blk>>>(value, Wv, bv, vp);
    scores_kernel<<<dim3(S_ / 64, S_ / 64, BH), blk>>>(qp, kp, attn);
    softmax_kernel<<<BH * S_, blk>>>(attn);
    ctx_kernel<<<dim3(S_ / 64, BH), blk>>>(attn, vp, cp);
    outproj_kernel<<<dim3(D_ / 64, MROWS / 64), blk>>>(cp, Wo, bo, out);
}

// round 2
// speedup vs baseline: 1.1941x; 1.1941x over previous
#include <cuda_runtime.h>
#include <math.h>

#define B_  8
#define S_  1024
#define D_  1024
#define H_  16
#define DK  64
#define BH  (B_ * H_)        // 128
#define MROWS (B_ * S_)      // 8192

// Scratch (no allocations allowed)
__device__ float g_q[(size_t)B_ * H_ * S_ * DK];
__device__ float g_k[(size_t)B_ * H_ * S_ * DK];
__device__ float g_v[(size_t)B_ * H_ * S_ * DK];
__device__ float g_ctx[(size_t)B_ * H_ * S_ * DK];
__device__ float g_attn[(size_t)B_ * H_ * S_ * S_];   // fallback if attn not in d_out

// ---------------------------------------------------------------------------
// Projection GEMM: treats all H heads as one 1024-wide N dimension.
// C[m, n] = sum_k X[m,k] * W[h][k][j] + bias[h][j],  n = h*64+j, m = b*1024+s
// Output layout: out[((b*H+h)*S+s)*64 + j]
// grid = (D_/128, MROWS/128), block = 256, tile 128x128x16, micro 8x8
// ---------------------------------------------------------------------------
__global__ __launch_bounds__(256) void proj_kernel(
    const float* __restrict__ X,      // [MROWS, D_]
    const float* __restrict__ W,      // [H_, D_, DK]
    const float* __restrict__ bias,   // [H_, DK]
    float* __restrict__ out)          // [B_, H_, S_, DK]
{
    __shared__ float As[16][132];   // As[k][m]
    __shared__ float Bs[16][132];   // Bs[k][n]
    const int tid = threadIdx.x;
    const int tx = tid & 15, ty = tid >> 4;
    const int n0 = blockIdx.x * 128;
    const int m0 = blockIdx.y * 128;
    float acc[8][8] = {};

    for (int k0 = 0; k0 < D_; k0 += 16) {
        #pragma unroll
        for (int i = 0; i < 2; i++) {            // A: 128 rows x 16 k (transposed)
            int lin = tid + i * 256;             // 0..511
            int r = lin >> 2;                    // 0..127
            int kq = (lin & 3) * 4;
            float4 v = *(const float4*)&X[(size_t)(m0 + r) * D_ + k0 + kq];
            As[kq + 0][r] = v.x; As[kq + 1][r] = v.y;
            As[kq + 2][r] = v.z; As[kq + 3][r] = v.w;
        }
        #pragma unroll
        for (int i = 0; i < 2; i++) {            // B: 16 k x 128 n
            int lin = tid + i * 256;
            int kk = lin >> 5;                   // 0..15
            int c = (lin & 31) * 4;              // 0..124
            int n = n0 + c;
            int h = n >> 6, j = n & 63;
            *(float4*)&Bs[kk][c] =
                *(const float4*)&W[((size_t)h * D_ + (k0 + kk)) * DK + j];
        }
        __syncthreads();
        #pragma unroll
        for (int kk = 0; kk < 16; kk++) {
            float4 a0 = *(const float4*)&As[kk][ty * 8];
            float4 a1 = *(const float4*)&As[kk][ty * 8 + 4];
            float4 b0 = *(const float4*)&Bs[kk][tx * 8];
            float4 b1 = *(const float4*)&Bs[kk][tx * 8 + 4];
            float a8[8] = {a0.x,a0.y,a0.z,a0.w,a1.x,a1.y,a1.z,a1.w};
            float b8[8] = {b0.x,b0.y,b0.z,b0.w,b1.x,b1.y,b1.z,b1.w};
            #pragma unroll
            for (int i = 0; i < 8; i++)
                #pragma unroll
                for (int j = 0; j < 8; j++)
                    acc[i][j] += a8[i] * b8[j];
        }
        __syncthreads();
    }
    // epilogue: thread columns n0+tx*8 .. +7 lie within one head (tx*8 % 64 <= 56)
    const int nbase = n0 + tx * 8;
    const int h = nbase >> 6, j0 = nbase & 63;
    float4 bia0 = *(const float4*)&bias[h * DK + j0];
    float4 bia1 = *(const float4*)&bias[h * DK + j0 + 4];
    #pragma unroll
    for (int i = 0; i < 8; i++) {
        int m = m0 + ty * 8 + i;
        int b = m >> 10, s = m & 1023;
        float* dst = out + (((size_t)(b * H_ + h)) * S_ + s) * DK + j0;
        float4 o0 = make_float4(acc[i][0] + bia0.x, acc[i][1] + bia0.y,
                                acc[i][2] + bia0.z, acc[i][3] + bia0.w);
        float4 o1 = make_float4(acc[i][4] + bia1.x, acc[i][5] + bia1.y,
                                acc[i][6] + bia1.z, acc[i][7] + bia1.w);
        *(float4*)&dst[0] = o0;
        *(float4*)&dst[4] = o1;
    }
}

// ---------------------------------------------------------------------------
// Output projection: C[m,n] = sum_k ctx_layout[m,k] * Wo[k,n] + bo[n]
// A[m,k] = ctx[((b*H + (k>>6))*S + s)*64 + (k&63)],  m = b*1024+s
// grid = (D_/128, MROWS/128), block = 256
// ---------------------------------------------------------------------------
__global__ __launch_bounds__(256) void outproj_kernel(
    const float* __restrict__ ctx, const float* __restrict__ Wo,
    const float* __restrict__ bo, float* __restrict__ out)
{
    __shared__ float As[16][132];
    __shared__ float Bs[16][132];
    const int tid = threadIdx.x;
    const int tx = tid & 15, ty = tid >> 4;
    const int n0 = blockIdx.x * 128;
    const int m0 = blockIdx.y * 128;
    float acc[8][8] = {};

    for (int k0 = 0; k0 < D_; k0 += 16) {
        #pragma unroll
        for (int i = 0; i < 2; i++) {
            int lin = tid + i * 256;
            int r = lin >> 2;
            int kq = (lin & 3) * 4;
            int m = m0 + r;
            int b = m >> 10, s = m & 1023;
            int kg = k0 + kq;
            int h = kg >> 6, j = kg & 63;
            float4 v = *(const float4*)&ctx[(((size_t)b * H_ + h) * S_ + s) * DK + j];
            As[kq + 0][r] = v.x; As[kq + 1][r] = v.y;
            As[kq + 2][r] = v.z; As[kq + 3][r] = v.w;
        }
        #pragma unroll
        for (int i = 0; i < 2; i++) {
            int lin = tid + i * 256;
            int kk = lin >> 5;
            int c = (lin & 31) * 4;
            *(float4*)&Bs[kk][c] = *(const float4*)&Wo[(size_t)(k0 + kk) * D_ + n0 + c];
        }
        __syncthreads();
        #pragma unroll
        for (int kk = 0; kk < 16; kk++) {
            float4 a0 = *(const float4*)&As[kk][ty * 8];
            float4 a1 = *(const float4*)&As[kk][ty * 8 + 4];
            float4 b0 = *(const float4*)&Bs[kk][tx * 8];
            float4 b1 = *(const float4*)&Bs[kk][tx * 8 + 4];
            float a8[8] = {a0.x,a0.y,a0.z,a0.w,a1.x,a1.y,a1.z,a1.w};
            float b8[8] = {b0.x,b0.y,b0.z,b0.w,b1.x,b1.y,b1.z,b1.w};
            #pragma unroll
            for (int i = 0; i < 8; i++)
                #pragma unroll
                for (int j = 0; j < 8; j++)
                    acc[i][j] += a8[i] * b8[j];
        }
        __syncthreads();
    }
    float4 bo0 = *(const float4*)&bo[n0 + tx * 8];
    float4 bo1 = *(const float4*)&bo[n0 + tx * 8 + 4];
    #pragma unroll
    for (int i = 0; i < 8; i++) {
        int m = m0 + ty * 8 + i;
        float* dst = out + (size_t)m * D_ + n0 + tx * 8;
        float4 o0 = make_float4(acc[i][0] + bo0.x, acc[i][1] + bo0.y,
                                acc[i][2] + bo0.z, acc[i][3] + bo0.w);
        float4 o1 = make_float4(acc[i][4] + bo1.x, acc[i][5] + bo1.y,
                                acc[i][6] + bo1.z, acc[i][7] + bo1.w);
        *(float4*)&dst[0] = o0;
        *(float4*)&dst[4] = o1;
    }
}

// ---------------------------------------------------------------------------
// Fused scores + softmax: block owns (bh, 32 s-rows) and full t range.
// Computes QK^T/8 into smem (32x1024), softmaxes rows, writes attn once.
// grid = (S_/32, BH), block = 256, dynamic smem ~215.5 KB
// ---------------------------------------------------------------------------
#define SC_PAD 1032
#define KT_PAD 261
#define QT_PAD 65
#define FUSED_SMEM ((32 * SC_PAD + 64 * KT_PAD + 64 * QT_PAD) * sizeof(float))

__global__ __launch_bounds__(256) void scores_softmax_kernel(
    const float* __restrict__ q, const float* __restrict__ k,
    float* __restrict__ attn)
{
    extern __shared__ float smem[];
    float* sc  = smem;                        // [32][SC_PAD]
    float* KsT = smem + 32 * SC_PAD;          // [64][KT_PAD]  (k-major)
    float* QsT = KsT + 64 * KT_PAD;           // [64][QT_PAD]  (k-major)

    const int tid = threadIdx.x;
    const int bh = blockIdx.y;
    const int s0 = blockIdx.x * 32;
    const float* qb = q + (size_t)bh * S_ * DK;
    const float* kb = k + (size_t)bh * S_ * DK;

    // Stage Q tile transposed: QsT[k][r], r in 0..31
    #pragma unroll
    for (int i = 0; i < 2; i++) {
        int lin = tid + i * 256;              // 0..511
        int r = lin >> 4;                     // 0..31
        int kq = (lin & 15) * 4;
        float4 v = *(const float4*)&qb[(size_t)(s0 + r) * DK + kq];
        QsT[(kq + 0) * QT_PAD + r] = v.x;
        QsT[(kq + 1) * QT_PAD + r] = v.y;
        QsT[(kq + 2) * QT_PAD + r] = v.z;
        QsT[(kq + 3) * QT_PAD + r] = v.w;
    }
    __syncthreads();

    const int txl = tid & 31;                 // t lane: t = txl + j*32
    const int tyl = tid >> 5;                 // s group: s = tyl*4 + i

    for (int t0 = 0; t0 < S_; t0 += 256) {
        // Stage K chunk transposed: KsT[k][t], t in 0..255
        #pragma unroll
        for (int i = 0; i < 16; i++) {
            int lin = tid + i * 256;          // 0..4095
            int t = lin >> 4;                 // 0..255
            int kq = (lin & 15) * 4;
            float4 v = *(const float4*)&kb[(size_t)(t0 + t) * DK + kq];
            KsT[(kq + 0) * KT_PAD + t] = v.x;
            KsT[(kq + 1) * KT_PAD + t] = v.y;
            KsT[(kq + 2) * KT_PAD + t] = v.z;
            KsT[(kq + 3) * KT_PAD + t] = v.w;
        }
        __syncthreads();

        float acc[4][8] = {};
        #pragma unroll
        for (int kk = 0; kk < 64; kk++) {
            float a4[4], b8[8];
            #pragma unroll
            for (int i = 0; i < 4; i++) a4[i] = QsT[kk * QT_PAD + tyl * 4 + i];
            #pragma unroll
            for (int j = 0; j < 8; j++) b8[j] = KsT[kk * KT_PAD + txl + j * 32];
            #pragma unroll
            for (int i = 0; i < 4; i++)
                #pragma unroll
                for (int j = 0; j < 8; j++)
                    acc[i][j] += a4[i] * b8[j];
        }
        #pragma unroll
        for (int i = 0; i < 4; i++)
            #pragma unroll
            for (int j = 0; j < 8; j++)
                sc[(tyl * 4 + i) * SC_PAD + t0 + txl + j * 32] = acc[i][j] * 0.125f;
        __syncthreads();
    }

    // Softmax: warp w handles rows w*4 .. w*4+3 (full 1024-wide rows)
    const int w = tid >> 5;
    const int lane = tid & 31;
    for (int r = 0; r < 4; r++) {
        const int row = w * 4 + r;
        float* prow = sc + row * SC_PAD;
        float4 v[8];
        float mx = -1e30f;
        #pragma unroll
        for (int j = 0; j < 8; j++) {
            v[j] = *(const float4*)&prow[lane * 4 + j * 128];
            mx = fmaxf(mx, fmaxf(fmaxf(v[j].x, v[j].y), fmaxf(v[j].z, v[j].w)));
        }
        #pragma unroll
        for (int off = 16; off > 0; off >>= 1)
            mx = fmaxf(mx, __shfl_xor_sync(0xffffffffu, mx, off));
        float sum = 0.f;
        #pragma unroll
        for (int j = 0; j < 8; j++) {
            v[j].x = __expf(v[j].x - mx); v[j].y = __expf(v[j].y - mx);
            v[j].z = __expf(v[j].z - mx); v[j].w = __expf(v[j].w - mx);
            sum += (v[j].x + v[j].y) + (v[j].z + v[j].w);
        }
        #pragma unroll
        for (int off = 16; off > 0; off >>= 1)
            sum += __shfl_xor_sync(0xffffffffu, sum, off);
        const float inv = 1.0f / sum;
        float* grow = attn + ((size_t)bh * S_ + s0 + row) * S_;
        #pragma unroll
        for (int j = 0; j < 8; j++) {
            float4 o = make_float4(v[j].x * inv, v[j].y * inv,
                                   v[j].z * inv, v[j].w * inv);
            *(float4*)&grow[lane * 4 + j * 128] = o;
        }
    }
}

// ---------------------------------------------------------------------------
// Context GEMM: ctx[bh,s,j] = sum_t attn[bh,s,t] * v[bh,t,j]
// grid = (S_/128, BH), block = 256, tile 128x64x32, micro 8x4
// ---------------------------------------------------------------------------
__global__ __launch_bounds__(256) void ctx_kernel(
    const float* __restrict__ attn, const float* __restrict__ v,
    float* __restrict__ ctx)
{
    __shared__ float AsT[32][132];
    __shared__ float Bs[32][68];
    const int tid = threadIdx.x;
    const int tx = tid & 15, ty = tid >> 4;
    const int bh = blockIdx.y;
    const int s0 = blockIdx.x * 128;
    const float* ab = attn + (size_t)bh * S_ * S_;
    const float* vb = v + (size_t)bh * S_ * DK;
    float acc[8][4] = {};

    for (int k0 = 0; k0 < S_; k0 += 32) {
        #pragma unroll
        for (int i = 0; i < 4; i++) {            // A: 128 rows x 32 t
            int lin = tid + i * 256;             // 0..1023
            int r = lin >> 3;                    // 0..127
            int kq = (lin & 7) * 4;
            float4 val = *(const float4*)&ab[(size_t)(s0 + r) * S_ + k0 + kq];
            AsT[kq + 0][r] = val.x; AsT[kq + 1][r] = val.y;
            AsT[kq + 2][r] = val.z; AsT[kq + 3][r] = val.w;
        }
        #pragma unroll
        for (int i = 0; i < 2; i++) {            // B: 32 t x 64 j
            int lin = tid + i * 256;             // 0..511
            int kk = lin >> 4;                   // 0..31
            int c = (lin & 15) * 4;              // 0..60
            *(float4*)&Bs[kk][c] = *(const float4*)&vb[(size_t)(k0 + kk) * DK + c];
        }
        __syncthreads();
        #pragma unroll
        for (int kk = 0; kk < 32; kk++) {
            float4 a0 = *(const float4*)&AsT[kk][ty * 8];
            float4 a1 = *(const float4*)&AsT[kk][ty * 8 + 4];
            float4 b  = *(const float4*)&Bs[kk][tx * 4];
            float a8[8] = {a0.x,a0.y,a0.z,a0.w,a1.x,a1.y,a1.z,a1.w};
            float b4[4] = {b.x,b.y,b.z,b.w};
            #pragma unroll
            for (int i = 0; i < 8; i++)
                #pragma unroll
                for (int j = 0; j < 4; j++)
                    acc[i][j] += a8[i] * b4[j];
        }
        __syncthreads();
    }
    #pragma unroll
    for (int i = 0; i < 8; i++) {
        float* dst = ctx + ((size_t)bh * S_ + s0 + ty * 8 + i) * DK + tx * 4;
        *(float4*)dst = make_float4(acc[i][0], acc[i][1], acc[i][2], acc[i][3]);
    }
}

// ---------------------------------------------------------------------------
extern "C" void kernel_launch(void* const* d_in, const int* in_sizes, int n_in,
                              void* d_out, int out_size)
{
    const float* query = (const float*)d_in[0];
    const float* key   = (const float*)d_in[1];
    const float* value = (const float*)d_in[2];
    const float* Wq    = (const float*)d_in[3];
    const float* bq    = (const float*)d_in[4];
    const float* Wk    = (const float*)d_in[5];
    const float* bk    = (const float*)d_in[6];
    const float* Wv    = (const float*)d_in[7];
    const float* bv    = (const float*)d_in[8];
    const float* Wo    = (const float*)d_in[9];
    const float* bo    = (const float*)d_in[10];
    float* out = (float*)d_out;

    float *qp, *kp, *vp, *cp, *attn_scratch;
    cudaGetSymbolAddress((void**)&qp, g_q);
    cudaGetSymbolAddress((void**)&kp, g_k);
    cudaGetSymbolAddress((void**)&vp, g_v);
    cudaGetSymbolAddress((void**)&cp, g_ctx);
    cudaGetSymbolAddress((void**)&attn_scratch, g_attn);

    const size_t out_elems  = (size_t)B_ * S_ * D_;
    const size_t attn_elems = (size_t)B_ * H_ * S_ * S_;
    float* attn = ((size_t)out_size >= out_elems + attn_elems)
                      ? (out + out_elems) : attn_scratch;

    static int smem_set = 0;
    if (!smem_set) {
        cudaFuncSetAttribute(scores_softmax_kernel,
                             cudaFuncAttributeMaxDynamicSharedMemorySize,
                             (int)FUSED_SMEM);
        smem_set = 1;
    }

    dim3 blk(256);
    proj_kernel<<<dim3(D_ / 128, MROWS / 128), blk>>>(query, Wq, bq, qp);
    proj_kernel<<<dim3(D_ / 128, MROWS / 128), blk>>>(key,   Wk, bk, kp);
    proj_kernel<<<dim3(D_ / 128, MROWS / 128), blk>>>(value, Wv, bv, vp);
    scores_softmax_kernel<<<dim3(S_ / 32, BH), blk, FUSED_SMEM>>>(qp, kp, attn);
    ctx_kernel<<<dim3(S_ / 128, BH), blk>>>(attn, vp, cp);
    outproj_kernel<<<dim3(D_ / 128, MROWS / 128), blk>>>(cp, Wo, bo, out);
}

// round 4
// speedup vs baseline: 2.0633x; 1.7278x over previous
#include <cuda_runtime.h>
#include <cuda_bf16.h>
#include <stdint.h>
#include <math.h>

#define B_  8
#define S_  1024
#define D_  1024
#define H_  16
#define DK  64
#define BH  (B_ * H_)
#define MROWS (B_ * S_)

typedef __nv_bfloat16 bf16;

// Scratch
__device__ float g_q[(size_t)B_ * H_ * S_ * DK];
__device__ float g_k[(size_t)B_ * H_ * S_ * DK];
__device__ float g_v[(size_t)B_ * H_ * S_ * DK];
__device__ float g_ctx[(size_t)B_ * H_ * S_ * DK];
__device__ float g_attn[(size_t)B_ * H_ * S_ * S_];

// ---------------------------------------------------------------------------
// helpers
// ---------------------------------------------------------------------------
__device__ __forceinline__ uint32_t s2u(const void* p) {
    uint32_t a;
    asm("{ .reg .u64 t; cvta.to.shared.u64 t, %1; cvt.u32.u64 %0, t; }"
        : "=r"(a) : "l"(p));
    return a;
}

__device__ __forceinline__ void ldsm4(uint32_t* r, uint32_t a) {
    asm volatile("ldmatrix.sync.aligned.m8n8.x4.shared.b16 {%0,%1,%2,%3}, [%4];"
        : "=r"(r[0]), "=r"(r[1]), "=r"(r[2]), "=r"(r[3]) : "r"(a));
}
__device__ __forceinline__ void ldsm4t(uint32_t* r, uint32_t a) {
    asm volatile("ldmatrix.sync.aligned.m8n8.x4.trans.shared.b16 {%0,%1,%2,%3}, [%4];"
        : "=r"(r[0]), "=r"(r[1]), "=r"(r[2]), "=r"(r[3]) : "r"(a));
}
__device__ __forceinline__ void mmabf(float* c, const uint32_t* a, const uint32_t* b) {
    asm volatile("mma.sync.aligned.m16n8k16.row.col.f32.bf16.bf16.f32 "
        "{%0,%1,%2,%3}, {%4,%5,%6,%7}, {%8,%9}, {%0,%1,%2,%3};"
        : "+f"(c[0]), "+f"(c[1]), "+f"(c[2]), "+f"(c[3])
        : "r"(a[0]), "r"(a[1]), "r"(a[2]), "r"(a[3]), "r"(b[0]), "r"(b[1]));
}

// split float4 into hi/lo bf16 pairs, store 8B each
__device__ __forceinline__ void cvt_pair_store(bf16* hi, bf16* lo, float4 v) {
    uint32_t h0, h1;
    asm("cvt.rn.bf16x2.f32 %0, %1, %2;" : "=r"(h0) : "f"(v.y), "f"(v.x));
    asm("cvt.rn.bf16x2.f32 %0, %1, %2;" : "=r"(h1) : "f"(v.w), "f"(v.z));
    float hx = __uint_as_float(h0 << 16), hy = __uint_as_float(h0 & 0xffff0000u);
    float hz = __uint_as_float(h1 << 16), hw = __uint_as_float(h1 & 0xffff0000u);
    uint32_t l0, l1;
    asm("cvt.rn.bf16x2.f32 %0, %1, %2;" : "=r"(l0) : "f"(v.y - hy), "f"(v.x - hx));
    asm("cvt.rn.bf16x2.f32 %0, %1, %2;" : "=r"(l1) : "f"(v.w - hw), "f"(v.z - hz));
    *(uint2*)hi = make_uint2(h0, h1);
    *(uint2*)lo = make_uint2(l0, l1);
}

#define ASTR 40      // [m][k32] stride (bf16), pad 8 -> conflict-free ldmatrix
#define BSTR 72      // [k32][n64] stride

// Warp 64x32 tile over one k32 chunk. BTRANS: B smem [k][n] via ldmatrix.trans;
// else B smem [n][k32] (col-major B), plain ldmatrix.
template<bool BTRANS, int AS, int BS>
__device__ __forceinline__ void warp_chunk(
    const bf16* Ah, const bf16* Al, const bf16* Bh, const bf16* Bl,
    int m_off, int n_off, int lane, float acc[4][4][4])
{
    #pragma unroll
    for (int kk = 0; kk < 32; kk += 16) {
        uint32_t a[4][4], b0[2][4], b1[2][4];
        #pragma unroll
        for (int mi = 0; mi < 4; mi++)
            ldsm4(a[mi], s2u(Ah + (m_off + mi * 16 + (lane & 15)) * AS + kk + (lane >> 4) * 8));
        #pragma unroll
        for (int j = 0; j < 2; j++) {
            if (BTRANS)
                ldsm4t(b0[j], s2u(Bh + (kk + (lane & 15)) * BS + n_off + j * 16 + (lane >> 4) * 8));
            else
                ldsm4(b0[j], s2u(Bh + (n_off + j * 16 + (lane & 7) + ((lane >> 4) << 3)) * BS
                                 + kk + ((lane >> 3) & 1) * 8));
        }
        #pragma unroll
        for (int mi = 0; mi < 4; mi++)
            #pragma unroll
            for (int nj = 0; nj < 4; nj++)
                mmabf(acc[mi][nj], a[mi], &b0[nj >> 1][(nj & 1) * 2]);
        #pragma unroll
        for (int j = 0; j < 2; j++) {
            if (BTRANS)
                ldsm4t(b1[j], s2u(Bl + (kk + (lane & 15)) * BS + n_off + j * 16 + (lane >> 4) * 8));
            else
                ldsm4(b1[j], s2u(Bl + (n_off + j * 16 + (lane & 7) + ((lane >> 4) << 3)) * BS
                                 + kk + ((lane >> 3) & 1) * 8));
        }
        #pragma unroll
        for (int mi = 0; mi < 4; mi++)
            #pragma unroll
            for (int nj = 0; nj < 4; nj++)
                mmabf(acc[mi][nj], a[mi], &b1[nj >> 1][(nj & 1) * 2]);
        #pragma unroll
        for (int mi = 0; mi < 4; mi++)
            ldsm4(a[mi], s2u(Al + (m_off + mi * 16 + (lane & 15)) * AS + kk + (lane >> 4) * 8));
        #pragma unroll
        for (int mi = 0; mi < 4; mi++)
            #pragma unroll
            for (int nj = 0; nj < 4; nj++)
                mmabf(acc[mi][nj], a[mi], &b0[nj >> 1][(nj & 1) * 2]);
    }
}

// smem bytes: A(256x40)*2 bf16 x2 + B(32x72)*2 x2
#define SMEM_P ((256 * ASTR * 2 + 32 * BSTR * 2) * 2)
#define SMEM_S ((128 * ASTR * 2 + 128 * ASTR * 2) * 2)

// ---------------------------------------------------------------------------
// proj: out[((b*H+h)*S+s)*64+j] = sum_k X[m,k] W[h,k,j] + bias[h,j]
// grid (H_, MROWS/256), block 256; tile 256x64, K chunk 32
// ---------------------------------------------------------------------------
__global__ __launch_bounds__(256) void proj_mma(
    const float* __restrict__ X, const float* __restrict__ W,
    const float* __restrict__ bias, float* __restrict__ out)
{
    extern __shared__ bf16 sm[];
    bf16* Ah = sm;
    bf16* Al = Ah + 256 * ASTR;
    bf16* Bh = Al + 256 * ASTR;
    bf16* Bl = Bh + 32 * BSTR;
    const int tid = threadIdx.x, w = tid >> 5, lane = tid & 31;
    const int h = blockIdx.x, m0 = blockIdx.y * 256;
    const int m_off = (w & 3) * 64, n_off = (w >> 2) * 32;
    const float* Wh = W + (size_t)h * D_ * DK;
    float acc[4][4][4] = {};

    for (int k0 = 0; k0 < D_; k0 += 32) {
        #pragma unroll
        for (int i = 0; i < 8; i++) {
            int lin = tid + i * 256;
            int r = lin >> 3, c4 = (lin & 7) * 4;
            float4 v = *(const float4*)&X[(size_t)(m0 + r) * D_ + k0 + c4];
            cvt_pair_store(&Ah[r * ASTR + c4], &Al[r * ASTR + c4], v);
        }
        #pragma unroll
        for (int i = 0; i < 2; i++) {
            int lin = tid + i * 256;
            int r = lin >> 4, c4 = (lin & 15) * 4;
            float4 v = *(const float4*)&Wh[(size_t)(k0 + r) * DK + c4];
            cvt_pair_store(&Bh[r * BSTR + c4], &Bl[r * BSTR + c4], v);
        }
        __syncthreads();
        warp_chunk<true, ASTR, BSTR>(Ah, Al, Bh, Bl, m_off, n_off, lane, acc);
        __syncthreads();
    }
    const int g = lane >> 2, q = lane & 3;
    #pragma unroll
    for (int mi = 0; mi < 4; mi++) {
        int m = m0 + m_off + mi * 16 + g;
        int b = m >> 10, s = m & 1023;
        float* d0 = out + (((size_t)(b * H_ + h)) * S_ + s) * DK;
        float* d1 = out + (((size_t)(b * H_ + h)) * S_ + s + 8) * DK;
        #pragma unroll
        for (int nj = 0; nj < 4; nj++) {
            int col = n_off + nj * 8 + q * 2;
            float bb0 = bias[h * DK + col], bb1 = bias[h * DK + col + 1];
            *(float2*)&d0[col] = make_float2(acc[mi][nj][0] + bb0, acc[mi][nj][1] + bb1);
            *(float2*)&d1[col] = make_float2(acc[mi][nj][2] + bb0, acc[mi][nj][3] + bb1);
        }
    }
}

// ---------------------------------------------------------------------------
// scores: attn[bh,s,t] = q.k/8; tile 128x128, K=64 (2 chunks)
// grid (8, 8, BH), block 256
// ---------------------------------------------------------------------------
__global__ __launch_bounds__(256) void scores_mma(
    const float* __restrict__ qv, const float* __restrict__ kv,
    float* __restrict__ attn)
{
    extern __shared__ bf16 sm[];
    bf16* Ah = sm;
    bf16* Al = Ah + 128 * ASTR;
    bf16* Bh = Al + 128 * ASTR;
    bf16* Bl = Bh + 128 * ASTR;
    const int tid = threadIdx.x, w = tid >> 5, lane = tid & 31;
    const int t0 = blockIdx.x * 128, s0 = blockIdx.y * 128, bh = blockIdx.z;
    const int m_off = (w & 1) * 64, n_off = (w >> 1) * 32;
    const float* qb = qv + (size_t)bh * S_ * DK;
    const float* kb = kv + (size_t)bh * S_ * DK;
    float acc[4][4][4] = {};

    for (int k0 = 0; k0 < DK; k0 += 32) {
        #pragma unroll
        for (int i = 0; i < 4; i++) {
            int lin = tid + i * 256;
            int r = lin >> 3, c4 = (lin & 7) * 4;
            float4 v = *(const float4*)&qb[(size_t)(s0 + r) * DK + k0 + c4];
            cvt_pair_store(&Ah[r * ASTR + c4], &Al[r * ASTR + c4], v);
        }
        #pragma unroll
        for (int i = 0; i < 4; i++) {
            int lin = tid + i * 256;
            int r = lin >> 3, c4 = (lin & 7) * 4;
            float4 v = *(const float4*)&kb[(size_t)(t0 + r) * DK + k0 + c4];
            cvt_pair_store(&Bh[r * ASTR + c4], &Bl[r * ASTR + c4], v);
        }
        __syncthreads();
        warp_chunk<false, ASTR, ASTR>(Ah, Al, Bh, Bl, m_off, n_off, lane, acc);
        __syncthreads();
    }
    const int g = lane >> 2, q = lane & 3;
    #pragma unroll
    for (int mi = 0; mi < 4; mi++) {
        int s = s0 + m_off + mi * 16 + g;
        float* d0 = attn + ((size_t)bh * S_ + s) * S_ + t0;
        float* d1 = attn + ((size_t)bh * S_ + s + 8) * S_ + t0;
        #pragma unroll
        for (int nj = 0; nj < 4; nj++) {
            int col = n_off + nj * 8 + q * 2;
            *(float2*)&d0[col] = make_float2(acc[mi][nj][0] * 0.125f, acc[mi][nj][1] * 0.125f);
            *(float2*)&d1[col] = make_float2(acc[mi][nj][2] * 0.125f, acc[mi][nj][3] * 0.125f);
        }
    }
}

// ---------------------------------------------------------------------------
// softmax rows in place
// ---------------------------------------------------------------------------
__global__ __launch_bounds__(256) void softmax_kernel(float* __restrict__ attn)
{
    const size_t row = blockIdx.x;
    float* p = attn + row * S_;
    const int tid = threadIdx.x;
    float4 v = ((float4*)p)[tid];

    __shared__ float red[256];
    float m = fmaxf(fmaxf(v.x, v.y), fmaxf(v.z, v.w));
    red[tid] = m;
    __syncthreads();
    #pragma unroll
    for (int off = 128; off > 0; off >>= 1) {
        if (tid < off) red[tid] = fmaxf(red[tid], red[tid + off]);
        __syncthreads();
    }
    const float mx = red[0];
    __syncthreads();
    float e0 = __expf(v.x - mx), e1 = __expf(v.y - mx);
    float e2 = __expf(v.z - mx), e3 = __expf(v.w - mx);
    red[tid] = (e0 + e1) + (e2 + e3);
    __syncthreads();
    #pragma unroll
    for (int off = 128; off > 0; off >>= 1) {
        if (tid < off) red[tid] += red[tid + off];
        __syncthreads();
    }
    const float inv = 1.0f / red[0];
    ((float4*)p)[tid] = make_float4(e0 * inv, e1 * inv, e2 * inv, e3 * inv);
}

// ---------------------------------------------------------------------------
// ctx: ctx[bh,s,j] = sum_t attn[bh,s,t] v[bh,t,j]; tile 256x64, K=1024
// grid (MROWS: S_/256=4, BH), block 256
// ---------------------------------------------------------------------------
__global__ __launch_bounds__(256) void ctx_mma(
    const float* __restrict__ attn, const float* __restrict__ vv,
    float* __restrict__ ctx)
{
    extern __shared__ bf16 sm[];
    bf16* Ah = sm;
    bf16* Al = Ah + 256 * ASTR;
    bf16* Bh = Al + 256 * ASTR;
    bf16* Bl = Bh + 32 * BSTR;
    const int tid = threadIdx.x, w = tid >> 5, lane = tid & 31;
    const int s0 = blockIdx.x * 256, bh = blockIdx.y;
    const int m_off = (w & 3) * 64, n_off = (w >> 2) * 32;
    const float* ab = attn + (size_t)bh * S_ * S_;
    const float* vb = vv + (size_t)bh * S_ * DK;
    float acc[4][4][4] = {};

    for (int k0 = 0; k0 < S_; k0 += 32) {
        #pragma unroll
        for (int i = 0; i < 8; i++) {
            int lin = tid + i * 256;
            int r = lin >> 3, c4 = (lin & 7) * 4;
            float4 v = *(const float4*)&ab[(size_t)(s0 + r) * S_ + k0 + c4];
            cvt_pair_store(&Ah[r * ASTR + c4], &Al[r * ASTR + c4], v);
        }
        #pragma unroll
        for (int i = 0; i < 2; i++) {
            int lin = tid + i * 256;
            int r = lin >> 4, c4 = (lin & 15) * 4;
            float4 v = *(const float4*)&vb[(size_t)(k0 + r) * DK + c4];
            cvt_pair_store(&Bh[r * BSTR + c4], &Bl[r * BSTR + c4], v);
        }
        __syncthreads();
        warp_chunk<true, ASTR, BSTR>(Ah, Al, Bh, Bl, m_off, n_off, lane, acc);
        __syncthreads();
    }
    const int g = lane >> 2, q = lane & 3;
    #pragma unroll
    for (int mi = 0; mi < 4; mi++) {
        int s = s0 + m_off + mi * 16 + g;
        float* d0 = ctx + ((size_t)bh * S_ + s) * DK;
        float* d1 = ctx + ((size_t)bh * S_ + s + 8) * DK;
        #pragma unroll
        for (int nj = 0; nj < 4; nj++) {
            int col = n_off + nj * 8 + q * 2;
            *(float2*)&d0[col] = make_float2(acc[mi][nj][0], acc[mi][nj][1]);
            *(float2*)&d1[col] = make_float2(acc[mi][nj][2], acc[mi][nj][3]);
        }
    }
}

// ---------------------------------------------------------------------------
// outproj: out[m,n] = sum_k ctxlay[m,k] Wo[k,n] + bo[n]; tile 256x64
// grid (D_/64, MROWS/256), block 256
// ---------------------------------------------------------------------------
__global__ __launch_bounds__(256) void outproj_mma(
    const float* __restrict__ ctx, const float* __restrict__ Wo,
    const float* __restrict__ bo, float* __restrict__ out)
{
    extern __shared__ bf16 sm[];
    bf16* Ah = sm;
    bf16* Al = Ah + 256 * ASTR;
    bf16* Bh = Al + 256 * ASTR;
    bf16* Bl = Bh + 32 * BSTR;
    const int tid = threadIdx.x, w = tid >> 5, lane = tid & 31;
    const int n0 = blockIdx.x * 64, m0 = blockIdx.y * 256;
    const int m_off = (w & 3) * 64, n_off = (w >> 2) * 32;
    float acc[4][4][4] = {};

    for (int k0 = 0; k0 < D_; k0 += 32) {
        const int h = k0 >> 6, j0 = k0 & 63;
        #pragma unroll
        for (int i = 0; i < 8; i++) {
            int lin = tid + i * 256;
            int r = lin >> 3, c4 = (lin & 7) * 4;
            int m = m0 + r;
            int b = m >> 10, s = m & 1023;
            float4 v = *(const float4*)&ctx[(((size_t)b * H_ + h) * S_ + s) * DK + j0 + c4];
            cvt_pair_store(&Ah[r * ASTR + c4], &Al[r * ASTR + c4], v);
        }
        #pragma unroll
        for (int i = 0; i < 2; i++) {
            int lin = tid + i * 256;
            int r = lin >> 4, c4 = (lin & 15) * 4;
            float4 v = *(const float4*)&Wo[(size_t)(k0 + r) * D_ + n0 + c4];
            cvt_pair_store(&Bh[r * BSTR + c4], &Bl[r * BSTR + c4], v);
        }
        __syncthreads();
        warp_chunk<true, ASTR, BSTR>(Ah, Al, Bh, Bl, m_off, n_off, lane, acc);
        __syncthreads();
    }
    const int g = lane >> 2, q = lane & 3;
    #pragma unroll
    for (int mi = 0; mi < 4; mi++) {
        int m = m0 + m_off + mi * 16 + g;
        float* d0 = out + (size_t)m * D_ + n0;
        float* d1 = out + (size_t)(m + 8) * D_ + n0;
        #pragma unroll
        for (int nj = 0; nj < 4; nj++) {
            int col = n_off + nj * 8 + q * 2;
            float bb0 = bo[n0 + col], bb1 = bo[n0 + col + 1];
            *(float2*)&d0[col] = make_float2(acc[mi][nj][0] + bb0, acc[mi][nj][1] + bb1);
            *(float2*)&d1[col] = make_float2(acc[mi][nj][2] + bb0, acc[mi][nj][3] + bb1);
        }
    }
}

// ---------------------------------------------------------------------------
extern "C" void kernel_launch(void* const* d_in, const int* in_sizes, int n_in,
                              void* d_out, int out_size)
{
    const float* query = (const float*)d_in[0];
    const float* key   = (const float*)d_in[1];
    const float* value = (const float*)d_in[2];
    const float* Wq    = (const float*)d_in[3];
    const float* bq    = (const float*)d_in[4];
    const float* Wk    = (const float*)d_in[5];
    const float* bk    = (const float*)d_in[6];
    const float* Wv    = (const float*)d_in[7];
    const float* bv    = (const float*)d_in[8];
    const float* Wo    = (const float*)d_in[9];
    const float* bo    = (const float*)d_in[10];
    float* out = (float*)d_out;

    float *qp, *kp, *vp, *cp, *attn_scratch;
    cudaGetSymbolAddress((void**)&qp, g_q);
    cudaGetSymbolAddress((void**)&kp, g_k);
    cudaGetSymbolAddress((void**)&vp, g_v);
    cudaGetSymbolAddress((void**)&cp, g_ctx);
    cudaGetSymbolAddress((void**)&attn_scratch, g_attn);

    const size_t out_elems  = (size_t)B_ * S_ * D_;
    const size_t attn_elems = (size_t)B_ * H_ * S_ * S_;
    float* attn = ((size_t)out_size >= out_elems + attn_elems)
                      ? (out + out_elems) : attn_scratch;

    static int smem_set = 0;
    if (!smem_set) {
        cudaFuncSetAttribute(proj_mma, cudaFuncAttributeMaxDynamicSharedMemorySize, SMEM_P);
        cudaFuncSetAttribute(ctx_mma, cudaFuncAttributeMaxDynamicSharedMemorySize, SMEM_P);
        cudaFuncSetAttribute(outproj_mma, cudaFuncAttributeMaxDynamicSharedMemorySize, SMEM_P);
        cudaFuncSetAttribute(scores_mma, cudaFuncAttributeMaxDynamicSharedMemorySize, SMEM_S);
        smem_set = 1;
    }

    proj_mma<<<dim3(H_, MROWS / 256), 256, SMEM_P>>>(query, Wq, bq, qp);
    proj_mma<<<dim3(H_, MROWS / 256), 256, SMEM_P>>>(key,   Wk, bk, kp);
    proj_mma<<<dim3(H_, MROWS / 256), 256, SMEM_P>>>(value, Wv, bv, vp);
    scores_mma<<<dim3(S_ / 128, S_ / 128, BH), 256, SMEM_S>>>(qp, kp, attn);
    softmax_kernel<<<BH * S_, 256>>>(attn);
    ctx_mma<<<dim3(S_ / 256, BH), 256, SMEM_P>>>(attn, vp, cp);
    outproj_mma<<<dim3(D_ / 64, MROWS / 256), 256, SMEM_P>>>(cp, Wo, bo, out);
}

// round 7
// speedup vs baseline: 2.3815x; 1.1543x over previous
#include <cuda_runtime.h>
#include <cuda_bf16.h>
#include <stdint.h>
#include <math.h>

#define B_  8
#define S_  1024
#define D_  1024
#define H_  16
#define DK  64
#define BH  (B_ * H_)
#define MROWS (B_ * S_)

typedef __nv_bfloat16 bf16;

// Scratch: q/k/v as bf16 hi/lo planes; ctx fp32; attn fallback
__device__ bf16 g_qh[(size_t)BH * S_ * DK];
__device__ bf16 g_ql[(size_t)BH * S_ * DK];
__device__ bf16 g_kh[(size_t)BH * S_ * DK];
__device__ bf16 g_kl[(size_t)BH * S_ * DK];
__device__ bf16 g_vh[(size_t)BH * S_ * DK];
__device__ bf16 g_vl[(size_t)BH * S_ * DK];
__device__ float g_ctx[(size_t)BH * S_ * DK];
__device__ float g_attn[(size_t)BH * S_ * S_];

// ---------------------------------------------------------------------------
__device__ __forceinline__ uint32_t s2u(const void* p) {
    uint32_t a;
    asm("{ .reg .u64 t; cvta.to.shared.u64 t, %1; cvt.u32.u64 %0, t; }"
        : "=r"(a) : "l"(p));
    return a;
}
__device__ __forceinline__ void ldsm4(uint32_t* r, uint32_t a) {
    asm volatile("ldmatrix.sync.aligned.m8n8.x4.shared.b16 {%0,%1,%2,%3}, [%4];"
        : "=r"(r[0]), "=r"(r[1]), "=r"(r[2]), "=r"(r[3]) : "r"(a));
}
__device__ __forceinline__ void ldsm4t(uint32_t* r, uint32_t a) {
    asm volatile("ldmatrix.sync.aligned.m8n8.x4.trans.shared.b16 {%0,%1,%2,%3}, [%4];"
        : "=r"(r[0]), "=r"(r[1]), "=r"(r[2]), "=r"(r[3]) : "r"(a));
}
__device__ __forceinline__ void mmabf(float* c, const uint32_t* a, const uint32_t* b) {
    asm volatile("mma.sync.aligned.m16n8k16.row.col.f32.bf16.bf16.f32 "
        "{%0,%1,%2,%3}, {%4,%5,%6,%7}, {%8,%9}, {%0,%1,%2,%3};"
        : "+f"(c[0]), "+f"(c[1]), "+f"(c[2]), "+f"(c[3])
        : "r"(a[0]), "r"(a[1]), "r"(a[2]), "r"(a[3]), "r"(b[0]), "r"(b[1]));
}
__device__ __forceinline__ uint32_t packbf(float lo_e, float hi_e) {
    uint32_t r;
    asm("cvt.rn.bf16x2.f32 %0, %1, %2;" : "=r"(r) : "f"(hi_e), "f"(lo_e));
    return r;
}
// split float4 into hi/lo bf16 pairs, store 8B each (for proj A staging)
__device__ __forceinline__ void cvt_pair_store(bf16* hi, bf16* lo, float4 v) {
    uint32_t h0 = packbf(v.x, v.y), h1 = packbf(v.z, v.w);
    float hx = __uint_as_float(h0 << 16), hy = __uint_as_float(h0 & 0xffff0000u);
    float hz = __uint_as_float(h1 << 16), hw = __uint_as_float(h1 & 0xffff0000u);
    uint32_t l0 = packbf(v.x - hx, v.y - hy), l1 = packbf(v.z - hz, v.w - hw);
    *(uint2*)hi = make_uint2(h0, h1);
    *(uint2*)lo = make_uint2(l0, l1);
}
__device__ __forceinline__ void cpa16(uint32_t dst, const void* src) {
    asm volatile("cp.async.cg.shared.global [%0], [%1], 16;" :: "r"(dst), "l"(src));
}
#define CPA_COMMIT() asm volatile("cp.async.commit_group;" ::: "memory")
#define CPA_WAIT(n)  asm volatile("cp.async.wait_group %0;" :: "n"(n) : "memory")

#define ASTR 40
#define BSTR 72

// ===========================================================================
// proj: q/k/v projection, outputs bf16 hi/lo planes
// grid (H_, MROWS/256), block 256; tile 256x64, K chunk 32
// ===========================================================================
#define SMEM_P ((256 * ASTR * 2 + 32 * BSTR * 2) * 2)

__global__ __launch_bounds__(256) void proj_mma(
    const float* __restrict__ X, const float* __restrict__ W,
    const float* __restrict__ bias, bf16* __restrict__ outh,
    bf16* __restrict__ outl)
{
    extern __shared__ bf16 sm[];
    bf16* Ah = sm;
    bf16* Al = Ah + 256 * ASTR;
    bf16* Bh = Al + 256 * ASTR;
    bf16* Bl = Bh + 32 * BSTR;
    const int tid = threadIdx.x, w = tid >> 5, lane = tid & 31;
    const int h = blockIdx.x, m0 = blockIdx.y * 256;
    const int m_off = (w & 3) * 64, n_off = (w >> 2) * 32;
    const float* Wh = W + (size_t)h * D_ * DK;
    float acc[4][4][4] = {};

    for (int k0 = 0; k0 < D_; k0 += 32) {
        #pragma unroll
        for (int i = 0; i < 8; i++) {
            int lin = tid + i * 256;
            int r = lin >> 3, c4 = (lin & 7) * 4;
            float4 v = *(const float4*)&X[(size_t)(m0 + r) * D_ + k0 + c4];
            cvt_pair_store(&Ah[r * ASTR + c4], &Al[r * ASTR + c4], v);
        }
        #pragma unroll
        for (int i = 0; i < 2; i++) {
            int lin = tid + i * 256;
            int r = lin >> 4, c4 = (lin & 15) * 4;
            float4 v = *(const float4*)&Wh[(size_t)(k0 + r) * DK + c4];
            cvt_pair_store(&Bh[r * BSTR + c4], &Bl[r * BSTR + c4], v);
        }
        __syncthreads();
        #pragma unroll
        for (int kk = 0; kk < 32; kk += 16) {
            uint32_t a[4][4], b0[2][4], b1[2][4];
            #pragma unroll
            for (int mi = 0; mi < 4; mi++)
                ldsm4(a[mi], s2u(Ah + (m_off + mi * 16 + (lane & 15)) * ASTR + kk + (lane >> 4) * 8));
            #pragma unroll
            for (int j = 0; j < 2; j++)
                ldsm4t(b0[j], s2u(Bh + (kk + (lane & 15)) * BSTR + n_off + j * 16 + (lane >> 4) * 8));
            #pragma unroll
            for (int mi = 0; mi < 4; mi++)
                #pragma unroll
                for (int nj = 0; nj < 4; nj++)
                    mmabf(acc[mi][nj], a[mi], &b0[nj >> 1][(nj & 1) * 2]);
            #pragma unroll
            for (int j = 0; j < 2; j++)
                ldsm4t(b1[j], s2u(Bl + (kk + (lane & 15)) * BSTR + n_off + j * 16 + (lane >> 4) * 8));
            #pragma unroll
            for (int mi = 0; mi < 4; mi++)
                #pragma unroll
                for (int nj = 0; nj < 4; nj++)
                    mmabf(acc[mi][nj], a[mi], &b1[nj >> 1][(nj & 1) * 2]);
            #pragma unroll
            for (int mi = 0; mi < 4; mi++)
                ldsm4(a[mi], s2u(Al + (m_off + mi * 16 + (lane & 15)) * ASTR + kk + (lane >> 4) * 8));
            #pragma unroll
            for (int mi = 0; mi < 4; mi++)
                #pragma unroll
                for (int nj = 0; nj < 4; nj++)
                    mmabf(acc[mi][nj], a[mi], &b0[nj >> 1][(nj & 1) * 2]);
        }
        __syncthreads();
    }
    const int g = lane >> 2, q = lane & 3;
    #pragma unroll
    for (int mi = 0; mi < 4; mi++) {
        int m = m0 + m_off + mi * 16 + g;
        int b = m >> 10, s = m & 1023;
        size_t base0 = (((size_t)(b * H_ + h)) * S_ + s) * DK;
        size_t base1 = (((size_t)(b * H_ + h)) * S_ + s + 8) * DK;
        #pragma unroll
        for (int nj = 0; nj < 4; nj++) {
            int col = n_off + nj * 8 + q * 2;
            float bb0 = bias[h * DK + col], bb1 = bias[h * DK + col + 1];
            float v0 = acc[mi][nj][0] + bb0, v1 = acc[mi][nj][1] + bb1;
            float v2 = acc[mi][nj][2] + bb0, v3 = acc[mi][nj][3] + bb1;
            uint32_t hp0 = packbf(v0, v1), hp1 = packbf(v2, v3);
            float h0 = __uint_as_float(hp0 << 16), h1 = __uint_as_float(hp0 & 0xffff0000u);
            float h2 = __uint_as_float(hp1 << 16), h3 = __uint_as_float(hp1 & 0xffff0000u);
            uint32_t lp0 = packbf(v0 - h0, v1 - h1), lp1 = packbf(v2 - h2, v3 - h3);
            *(uint32_t*)&outh[base0 + col] = hp0;
            *(uint32_t*)&outl[base0 + col] = lp0;
            *(uint32_t*)&outh[base1 + col] = hp1;
            *(uint32_t*)&outl[base1 + col] = lp1;
        }
    }
}

// ===========================================================================
// Fused attention: QK^T/8 -> softmax -> attn (gmem) + ctx, per (bh, 32 s-rows)
// grid (S_/32, BH), block 256 (8 warps). Dynamic smem 215040 B.
// ===========================================================================
#define SC_STR 1032
#define SC_BYTES (32 * SC_STR * 4)            // 132096
#define KBUF_OFF SC_BYTES
#define KPLANE 18432                           // 128*72*2
#define KBUF_SZ (2 * KPLANE)                   // per buffer (hi+lo)
#define Q_OFF (KBUF_OFF + 2 * KBUF_SZ)         // 205824
#define FUSED_SMEM (Q_OFF + 2 * 4608)          // 215040

__global__ __launch_bounds__(256) void attn_fused(
    const bf16* __restrict__ qh, const bf16* __restrict__ ql,
    const bf16* __restrict__ kh, const bf16* __restrict__ kl,
    const bf16* __restrict__ vh, const bf16* __restrict__ vl,
    float* __restrict__ attn, float* __restrict__ ctx)
{
    extern __shared__ char smem[];
    float* sc = (float*)smem;
    bf16* QH = (bf16*)(smem + Q_OFF);
    bf16* QL = (bf16*)(smem + Q_OFF + 4608);

    const int tid = threadIdx.x, w = tid >> 5, lane = tid & 31;
    const int s0 = blockIdx.x * 32;
    const int bh = blockIdx.y;
    const size_t bhS = (size_t)bh * S_;
    const int wm = w & 1, wn = w >> 1;          // 2m x 4n warps
    const int g = lane >> 2, q = lane & 3;

    // --- stage Q (32x64, hi+lo planes): 512 uint4 over 2 iterations ---
    #pragma unroll
    for (int i = 0; i < 2; i++) {
        int lin = tid + i * 256;                // 0..511
        int plane = lin >> 8;                   // 0..1
        int rem = lin & 255;
        int row = rem >> 3;                     // 0..31
        int c16 = rem & 7;                      // 0..7 (8 bf16 chunks -> 64 cols)
        const bf16* src = (plane ? ql : qh) + (bhS + s0 + row) * DK + c16 * 8;
        bf16* dstp = (plane ? QL : QH) + row * BSTR + c16 * 8;
        *(uint4*)dstp = *(const uint4*)src;
    }

    // --- prologue: cp.async K tile 0 ---
    {
        uint32_t buf = s2u(smem + KBUF_OFF);
        #pragma unroll
        for (int i = 0; i < 8; i++) {
            int cid = tid + i * 256;
            int plane = cid >> 10, rem = cid & 1023;
            int row = rem >> 3, c16 = rem & 7;
            const bf16* src = (plane ? kl : kh) + (bhS + row) * DK + c16 * 8;
            cpa16(buf + plane * KPLANE + row * 144 + c16 * 16, src);
        }
        CPA_COMMIT();
    }
    __syncthreads();

    // --- preload Q fragments ---
    uint32_t aqh[4][4], aql[4][4];
    #pragma unroll
    for (int k4 = 0; k4 < 4; k4++) {
        ldsm4(aqh[k4], s2u(QH + (wm * 16 + (lane & 15)) * BSTR + k4 * 16 + (lane >> 4) * 8));
        ldsm4(aql[k4], s2u(QL + (wm * 16 + (lane & 15)) * BSTR + k4 * 16 + (lane >> 4) * 8));
    }

    // --- QK^T loop over 8 t-tiles ---
    for (int c = 0; c < 8; c++) {
        if (c < 7) {
            uint32_t buf = s2u(smem + KBUF_OFF + ((c + 1) & 1) * KBUF_SZ);
            int t1 = (c + 1) * 128;
            #pragma unroll
            for (int i = 0; i < 8; i++) {
                int cid = tid + i * 256;
                int plane = cid >> 10, rem = cid & 1023;
                int row = rem >> 3, c16 = rem & 7;
                const bf16* src = (plane ? kl : kh) + (bhS + t1 + row) * DK + c16 * 8;
                cpa16(buf + plane * KPLANE + row * 144 + c16 * 16, src);
            }
            CPA_COMMIT();
            CPA_WAIT(1);
        } else {
            CPA_WAIT(0);
        }
        __syncthreads();

        bf16* KHb = (bf16*)(smem + KBUF_OFF + (c & 1) * KBUF_SZ);
        bf16* KLb = (bf16*)(smem + KBUF_OFF + (c & 1) * KBUF_SZ + KPLANE);
        float acc[4][4] = {};
        #pragma unroll
        for (int k4 = 0; k4 < 4; k4++) {
            uint32_t bh4[2][4], bl4[2][4];
            #pragma unroll
            for (int j = 0; j < 2; j++)
                ldsm4(bh4[j], s2u(KHb + (wn * 32 + j * 16 + (lane & 7) + ((lane >> 4) << 3)) * BSTR
                                  + k4 * 16 + ((lane >> 3) & 1) * 8));
            #pragma unroll
            for (int nj = 0; nj < 4; nj++)
                mmabf(acc[nj], aqh[k4], &bh4[nj >> 1][(nj & 1) * 2]);
            #pragma unroll
            for (int j = 0; j < 2; j++)
                ldsm4(bl4[j], s2u(KLb + (wn * 32 + j * 16 + (lane & 7) + ((lane >> 4) << 3)) * BSTR
                                  + k4 * 16 + ((lane >> 3) & 1) * 8));
            #pragma unroll
            for (int nj = 0; nj < 4; nj++)
                mmabf(acc[nj], aqh[k4], &bl4[nj >> 1][(nj & 1) * 2]);
            #pragma unroll
            for (int nj = 0; nj < 4; nj++)
                mmabf(acc[nj], aql[k4], &bh4[nj >> 1][(nj & 1) * 2]);
        }
        // store scaled scores to smem
        #pragma unroll
        for (int nj = 0; nj < 4; nj++) {
            int col = c * 128 + wn * 32 + nj * 8 + q * 2;
            *(float2*)&sc[(wm * 16 + g) * SC_STR + col] =
                make_float2(acc[nj][0] * 0.125f, acc[nj][1] * 0.125f);
            *(float2*)&sc[(wm * 16 + g + 8) * SC_STR + col] =
                make_float2(acc[nj][2] * 0.125f, acc[nj][3] * 0.125f);
        }
        __syncthreads();
    }

    // --- prologue: cp.async V tile 0 (overlaps softmax) ---
    {
        uint32_t buf = s2u(smem + KBUF_OFF);
        #pragma unroll
        for (int i = 0; i < 8; i++) {
            int cid = tid + i * 256;
            int plane = cid >> 10, rem = cid & 1023;
            int row = rem >> 3, c16 = rem & 7;
            const bf16* src = (plane ? vl : vh) + (bhS + row) * DK + c16 * 8;
            cpa16(buf + plane * KPLANE + row * 144 + c16 * 16, src);
        }
        CPA_COMMIT();
    }

    // --- softmax: warp w handles rows w*4..w*4+3; write attn to gmem ---
    #pragma unroll
    for (int rr = 0; rr < 4; rr++) {
        const int row = w * 4 + rr;
        float* prow = sc + row * SC_STR;
        float4 v[8];
        float mx = -1e30f;
        #pragma unroll
        for (int j = 0; j < 8; j++) {
            v[j] = *(const float4*)&prow[lane * 4 + j * 128];
            mx = fmaxf(mx, fmaxf(fmaxf(v[j].x, v[j].y), fmaxf(v[j].z, v[j].w)));
        }
        #pragma unroll
        for (int off = 16; off > 0; off >>= 1)
            mx = fmaxf(mx, __shfl_xor_sync(0xffffffffu, mx, off));
        float sum = 0.f;
        #pragma unroll
        for (int j = 0; j < 8; j++) {
            v[j].x = __expf(v[j].x - mx); v[j].y = __expf(v[j].y - mx);
            v[j].z = __expf(v[j].z - mx); v[j].w = __expf(v[j].w - mx);
            sum += (v[j].x + v[j].y) + (v[j].z + v[j].w);
        }
        #pragma unroll
        for (int off = 16; off > 0; off >>= 1)
            sum += __shfl_xor_sync(0xffffffffu, sum, off);
        const float inv = 1.0f / sum;
        float* grow = attn + (bhS + s0 + row) * S_;
        #pragma unroll
        for (int j = 0; j < 8; j++) {
            float4 o = make_float4(v[j].x * inv, v[j].y * inv, v[j].z * inv, v[j].w * inv);
            *(float4*)&prow[lane * 4 + j * 128] = o;
            *(float4*)&grow[lane * 4 + j * 128] = o;
        }
    }
    __syncthreads();

    // --- ctx loop: acc over 8 V-tiles; warps 2m x 4(n16) ---
    float acc2[2][4] = {};
    for (int c = 0; c < 8; c++) {
        if (c < 7) {
            uint32_t buf = s2u(smem + KBUF_OFF + ((c + 1) & 1) * KBUF_SZ);
            int t1 = (c + 1) * 128;
            #pragma unroll
            for (int i = 0; i < 8; i++) {
                int cid = tid + i * 256;
                int plane = cid >> 10, rem = cid & 1023;
                int row = rem >> 3, c16 = rem & 7;
                const bf16* src = (plane ? vl : vh) + (bhS + t1 + row) * DK + c16 * 8;
                cpa16(buf + plane * KPLANE + row * 144 + c16 * 16, src);
            }
            CPA_COMMIT();
            CPA_WAIT(1);
        } else {
            CPA_WAIT(0);
        }
        __syncthreads();

        bf16* VHb = (bf16*)(smem + KBUF_OFF + (c & 1) * KBUF_SZ);
        bf16* VLb = (bf16*)(smem + KBUF_OFF + (c & 1) * KBUF_SZ + KPLANE);
        #pragma unroll
        for (int k4 = 0; k4 < 8; k4++) {
            // assemble attn A-fragments (hi/lo) from smem fp32
            int colb = c * 128 + k4 * 16 + q * 2;
            float2 x0 = *(const float2*)&sc[(wm * 16 + g) * SC_STR + colb];
            float2 x1 = *(const float2*)&sc[(wm * 16 + g + 8) * SC_STR + colb];
            float2 x2 = *(const float2*)&sc[(wm * 16 + g) * SC_STR + colb + 8];
            float2 x3 = *(const float2*)&sc[(wm * 16 + g + 8) * SC_STR + colb + 8];
            uint32_t ah[4], al[4];
            ah[0] = packbf(x0.x, x0.y); ah[1] = packbf(x1.x, x1.y);
            ah[2] = packbf(x2.x, x2.y); ah[3] = packbf(x3.x, x3.y);
            al[0] = packbf(x0.x - __uint_as_float(ah[0] << 16), x0.y - __uint_as_float(ah[0] & 0xffff0000u));
            al[1] = packbf(x1.x - __uint_as_float(ah[1] << 16), x1.y - __uint_as_float(ah[1] & 0xffff0000u));
            al[2] = packbf(x2.x - __uint_as_float(ah[2] << 16), x2.y - __uint_as_float(ah[2] & 0xffff0000u));
            al[3] = packbf(x3.x - __uint_as_float(ah[3] << 16), x3.y - __uint_as_float(ah[3] & 0xffff0000u));

            uint32_t bhf[4], blf[4];
            ldsm4t(bhf, s2u(VHb + (k4 * 16 + (lane & 15)) * BSTR + wn * 16 + (lane >> 4) * 8));
            ldsm4t(blf, s2u(VLb + (k4 * 16 + (lane & 15)) * BSTR + wn * 16 + (lane >> 4) * 8));
            #pragma unroll
            for (int nj = 0; nj < 2; nj++) {
                mmabf(acc2[nj], ah, &bhf[nj * 2]);
                mmabf(acc2[nj], ah, &blf[nj * 2]);
                mmabf(acc2[nj], al, &bhf[nj * 2]);
            }
        }
        __syncthreads();
    }

    // --- ctx epilogue ---
    #pragma unroll
    for (int nj = 0; nj < 2; nj++) {
        int col = wn * 16 + nj * 8 + q * 2;
        *(float2*)&ctx[(bhS + s0 + wm * 16 + g) * DK + col] = make_float2(acc2[nj][0], acc2[nj][1]);
        *(float2*)&ctx[(bhS + s0 + wm * 16 + g + 8) * DK + col] = make_float2(acc2[nj][2], acc2[nj][3]);
    }
}

// ===========================================================================
// outproj: out[m,n] = sum_k ctxlay[m,k] Wo[k,n] + bo[n]; tile 256x64
// ===========================================================================
__global__ __launch_bounds__(256) void outproj_mma(
    const float* __restrict__ ctx, const float* __restrict__ Wo,
    const float* __restrict__ bo, float* __restrict__ out)
{
    extern __shared__ bf16 sm[];
    bf16* Ah = sm;
    bf16* Al = Ah + 256 * ASTR;
    bf16* Bh = Al + 256 * ASTR;
    bf16* Bl = Bh + 32 * BSTR;
    const int tid = threadIdx.x, w = tid >> 5, lane = tid & 31;
    const int n0 = blockIdx.x * 64, m0 = blockIdx.y * 256;
    const int m_off = (w & 3) * 64, n_off = (w >> 2) * 32;
    float acc[4][4][4] = {};

    for (int k0 = 0; k0 < D_; k0 += 32) {
        const int h = k0 >> 6, j0 = k0 & 63;
        #pragma unroll
        for (int i = 0; i < 8; i++) {
            int lin = tid + i * 256;
            int r = lin >> 3, c4 = (lin & 7) * 4;
            int m = m0 + r;
            int b = m >> 10, s = m & 1023;
            float4 v = *(const float4*)&ctx[(((size_t)b * H_ + h) * S_ + s) * DK + j0 + c4];
            cvt_pair_store(&Ah[r * ASTR + c4], &Al[r * ASTR + c4], v);
        }
        #pragma unroll
        for (int i = 0; i < 2; i++) {
            int lin = tid + i * 256;
            int r = lin >> 4, c4 = (lin & 15) * 4;
            float4 v = *(const float4*)&Wo[(size_t)(k0 + r) * D_ + n0 + c4];
            cvt_pair_store(&Bh[r * BSTR + c4], &Bl[r * BSTR + c4], v);
        }
        __syncthreads();
        #pragma unroll
        for (int kk = 0; kk < 32; kk += 16) {
            uint32_t a[4][4], b0[2][4], b1[2][4];
            #pragma unroll
            for (int mi = 0; mi < 4; mi++)
                ldsm4(a[mi], s2u(Ah + (m_off + mi * 16 + (lane & 15)) * ASTR + kk + (lane >> 4) * 8));
            #pragma unroll
            for (int j = 0; j < 2; j++)
                ldsm4t(b0[j], s2u(Bh + (kk + (lane & 15)) * BSTR + n_off + j * 16 + (lane >> 4) * 8));
            #pragma unroll
            for (int mi = 0; mi < 4; mi++)
                #pragma unroll
                for (int nj = 0; nj < 4; nj++)
                    mmabf(acc[mi][nj], a[mi], &b0[nj >> 1][(nj & 1) * 2]);
            #pragma unroll
            for (int j = 0; j < 2; j++)
                ldsm4t(b1[j], s2u(Bl + (kk + (lane & 15)) * BSTR + n_off + j * 16 + (lane >> 4) * 8));
            #pragma unroll
            for (int mi = 0; mi < 4; mi++)
                #pragma unroll
                for (int nj = 0; nj < 4; nj++)
                    mmabf(acc[mi][nj], a[mi], &b1[nj >> 1][(nj & 1) * 2]);
            #pragma unroll
            for (int mi = 0; mi < 4; mi++)
                ldsm4(a[mi], s2u(Al + (m_off + mi * 16 + (lane & 15)) * ASTR + kk + (lane >> 4) * 8));
            #pragma unroll
            for (int mi = 0; mi < 4; mi++)
                #pragma unroll
                for (int nj = 0; nj < 4; nj++)
                    mmabf(acc[mi][nj], a[mi], &b0[nj >> 1][(nj & 1) * 2]);
        }
        __syncthreads();
    }
    const int g = lane >> 2, q = lane & 3;
    #pragma unroll
    for (int mi = 0; mi < 4; mi++) {
        int m = m0 + m_off + mi * 16 + g;
        float* d0 = out + (size_t)m * D_ + n0;
        float* d1 = out + (size_t)(m + 8) * D_ + n0;
        #pragma unroll
        for (int nj = 0; nj < 4; nj++) {
            int col = n_off + nj * 8 + q * 2;
            float bb0 = bo[n0 + col], bb1 = bo[n0 + col + 1];
            *(float2*)&d0[col] = make_float2(acc[mi][nj][0] + bb0, acc[mi][nj][1] + bb1);
            *(float2*)&d1[col] = make_float2(acc[mi][nj][2] + bb0, acc[mi][nj][3] + bb1);
        }
    }
}

// ---------------------------------------------------------------------------
extern "C" void kernel_launch(void* const* d_in, const int* in_sizes, int n_in,
                              void* d_out, int out_size)
{
    const float* query = (const float*)d_in[0];
    const float* key   = (const float*)d_in[1];
    const float* value = (const float*)d_in[2];
    const float* Wq    = (const float*)d_in[3];
    const float* bq    = (const float*)d_in[4];
    const float* Wk    = (const float*)d_in[5];
    const float* bk    = (const float*)d_in[6];
    const float* Wv    = (const float*)d_in[7];
    const float* bv    = (const float*)d_in[8];
    const float* Wo    = (const float*)d_in[9];
    const float* bo    = (const float*)d_in[10];
    float* out = (float*)d_out;

    bf16 *qh, *ql, *kh, *kl, *vh, *vl;
    float *cp, *attn_scratch;
    cudaGetSymbolAddress((void**)&qh, g_qh);
    cudaGetSymbolAddress((void**)&ql, g_ql);
    cudaGetSymbolAddress((void**)&kh, g_kh);
    cudaGetSymbolAddress((void**)&kl, g_kl);
    cudaGetSymbolAddress((void**)&vh, g_vh);
    cudaGetSymbolAddress((void**)&vl, g_vl);
    cudaGetSymbolAddress((void**)&cp, g_ctx);
    cudaGetSymbolAddress((void**)&attn_scratch, g_attn);

    const size_t out_elems  = (size_t)B_ * S_ * D_;
    const size_t attn_elems = (size_t)BH * S_ * S_;
    float* attn = ((size_t)out_size >= out_elems + attn_elems)
                      ? (out + out_elems) : attn_scratch;

    static int smem_set = 0;
    if (!smem_set) {
        cudaFuncSetAttribute(proj_mma, cudaFuncAttributeMaxDynamicSharedMemorySize, SMEM_P);
        cudaFuncSetAttribute(outproj_mma, cudaFuncAttributeMaxDynamicSharedMemorySize, SMEM_P);
        cudaFuncSetAttribute(attn_fused, cudaFuncAttributeMaxDynamicSharedMemorySize, FUSED_SMEM);
        smem_set = 1;
    }

    proj_mma<<<dim3(H_, MROWS / 256), 256, SMEM_P>>>(query, Wq, bq, qh, ql);
    proj_mma<<<dim3(H_, MROWS / 256), 256, SMEM_P>>>(key,   Wk, bk, kh, kl);
    proj_mma<<<dim3(H_, MROWS / 256), 256, SMEM_P>>>(value, Wv, bv, vh, vl);
    attn_fused<<<dim3(S_ / 32, BH), 256, FUSED_SMEM>>>(qh, ql, kh, kl, vh, vl, attn, cp);
    outproj_mma<<<dim3(D_ / 64, MROWS / 256), 256, SMEM_P>>>(cp, Wo, bo, out);
}

// round 8
// speedup vs baseline: 2.6371x; 1.1073x over previous
#include <cuda_runtime.h>
#include <cuda_bf16.h>
#include <stdint.h>
#include <math.h>

#define B_  8
#define S_  1024
#define D_  1024
#define H_  16
#define DK  64
#define BH  (B_ * H_)
#define MROWS (B_ * S_)

typedef __nv_bfloat16 bf16;

// bf16 hi/lo planes (pre-converted inputs, projections, ctx)
__device__ bf16 g_xh[3][(size_t)MROWS * D_];
__device__ bf16 g_xl[3][(size_t)MROWS * D_];
__device__ bf16 g_wh[3][(size_t)H_ * D_ * DK];
__device__ bf16 g_wl[3][(size_t)H_ * D_ * DK];
__device__ bf16 g_woh[(size_t)D_ * D_];
__device__ bf16 g_wol[(size_t)D_ * D_];
__device__ bf16 g_qh[(size_t)BH * S_ * DK];
__device__ bf16 g_ql[(size_t)BH * S_ * DK];
__device__ bf16 g_kh[(size_t)BH * S_ * DK];
__device__ bf16 g_kl[(size_t)BH * S_ * DK];
__device__ bf16 g_vh[(size_t)BH * S_ * DK];
__device__ bf16 g_vl[(size_t)BH * S_ * DK];
__device__ bf16 g_ch[(size_t)BH * S_ * DK];
__device__ bf16 g_cl[(size_t)BH * S_ * DK];
__device__ float g_attn[(size_t)BH * S_ * S_];

// ---------------------------------------------------------------------------
__device__ __forceinline__ uint32_t s2u(const void* p) {
    uint32_t a;
    asm("{ .reg .u64 t; cvta.to.shared.u64 t, %1; cvt.u32.u64 %0, t; }"
        : "=r"(a) : "l"(p));
    return a;
}
__device__ __forceinline__ void ldsm4(uint32_t* r, uint32_t a) {
    asm volatile("ldmatrix.sync.aligned.m8n8.x4.shared.b16 {%0,%1,%2,%3}, [%4];"
        : "=r"(r[0]), "=r"(r[1]), "=r"(r[2]), "=r"(r[3]) : "r"(a));
}
__device__ __forceinline__ void ldsm4t(uint32_t* r, uint32_t a) {
    asm volatile("ldmatrix.sync.aligned.m8n8.x4.trans.shared.b16 {%0,%1,%2,%3}, [%4];"
        : "=r"(r[0]), "=r"(r[1]), "=r"(r[2]), "=r"(r[3]) : "r"(a));
}
__device__ __forceinline__ void mmabf(float* c, const uint32_t* a, const uint32_t* b) {
    asm volatile("mma.sync.aligned.m16n8k16.row.col.f32.bf16.bf16.f32 "
        "{%0,%1,%2,%3}, {%4,%5,%6,%7}, {%8,%9}, {%0,%1,%2,%3};"
        : "+f"(c[0]), "+f"(c[1]), "+f"(c[2]), "+f"(c[3])
        : "r"(a[0]), "r"(a[1]), "r"(a[2]), "r"(a[3]), "r"(b[0]), "r"(b[1]));
}
__device__ __forceinline__ uint32_t packbf(float lo_e, float hi_e) {
    uint32_t r;
    asm("cvt.rn.bf16x2.f32 %0, %1, %2;" : "=r"(r) : "f"(hi_e), "f"(lo_e));
    return r;
}
__device__ __forceinline__ void cpa16(uint32_t dst, const void* src) {
    asm volatile("cp.async.cg.shared.global [%0], [%1], 16;" :: "r"(dst), "l"(src));
}
#define CPA_COMMIT() asm volatile("cp.async.commit_group;" ::: "memory")
#define CPA_WAIT(n)  asm volatile("cp.async.wait_group %0;" :: "n"(n) : "memory")

#define ASTR 40
#define BSTR 72

// Warp 64x32 tile over one k32 chunk (B smem [k][n], ldmatrix.trans).
__device__ __forceinline__ void warp_chunk(
    const bf16* Ah, const bf16* Al, const bf16* Bh, const bf16* Bl,
    int m_off, int n_off, int lane, float acc[4][4][4])
{
    #pragma unroll
    for (int kk = 0; kk < 32; kk += 16) {
        uint32_t a[4][4], b0[2][4], b1[2][4];
        #pragma unroll
        for (int mi = 0; mi < 4; mi++)
            ldsm4(a[mi], s2u(Ah + (m_off + mi * 16 + (lane & 15)) * ASTR + kk + (lane >> 4) * 8));
        #pragma unroll
        for (int j = 0; j < 2; j++)
            ldsm4t(b0[j], s2u(Bh + (kk + (lane & 15)) * BSTR + n_off + j * 16 + (lane >> 4) * 8));
        #pragma unroll
        for (int mi = 0; mi < 4; mi++)
            #pragma unroll
            for (int nj = 0; nj < 4; nj++)
                mmabf(acc[mi][nj], a[mi], &b0[nj >> 1][(nj & 1) * 2]);
        #pragma unroll
        for (int j = 0; j < 2; j++)
            ldsm4t(b1[j], s2u(Bl + (kk + (lane & 15)) * BSTR + n_off + j * 16 + (lane >> 4) * 8));
        #pragma unroll
        for (int mi = 0; mi < 4; mi++)
            #pragma unroll
            for (int nj = 0; nj < 4; nj++)
                mmabf(acc[mi][nj], a[mi], &b1[nj >> 1][(nj & 1) * 2]);
        #pragma unroll
        for (int mi = 0; mi < 4; mi++)
            ldsm4(a[mi], s2u(Al + (m_off + mi * 16 + (lane & 15)) * ASTR + kk + (lane >> 4) * 8));
        #pragma unroll
        for (int mi = 0; mi < 4; mi++)
            #pragma unroll
            for (int nj = 0; nj < 4; nj++)
                mmabf(acc[mi][nj], a[mi], &b0[nj >> 1][(nj & 1) * 2]);
    }
}

// ===========================================================================
// cvt: fp32 -> bf16 hi/lo planes
// ===========================================================================
__global__ __launch_bounds__(256) void cvt_kernel(
    const float* __restrict__ src, bf16* __restrict__ dh,
    bf16* __restrict__ dl, int n)
{
    int i = (blockIdx.x * 256 + threadIdx.x) * 4;
    if (i >= n) return;
    float4 v = *(const float4*)(src + i);
    uint32_t h0 = packbf(v.x, v.y), h1 = packbf(v.z, v.w);
    float hx = __uint_as_float(h0 << 16), hy = __uint_as_float(h0 & 0xffff0000u);
    float hz = __uint_as_float(h1 << 16), hw = __uint_as_float(h1 & 0xffff0000u);
    uint32_t l0 = packbf(v.x - hx, v.y - hy), l1 = packbf(v.z - hz, v.w - hw);
    *(uint2*)(dh + i) = make_uint2(h0, h1);
    *(uint2*)(dl + i) = make_uint2(l0, l1);
}

// ===========================================================================
// proj: all three projections (grid.z selects q/k/v), cp.async double-buffered
// grid (H_, MROWS/256, 3), block 256; tile 256x64, K chunk 32
// ===========================================================================
#define AB (256 * ASTR)                 // A plane elems per stage
#define BBE (32 * BSTR)                 // B plane elems per stage
#define STAGE_E (2 * AB + 2 * BBE)      // 25088 elems
#define SMEM_PJ (2 * STAGE_E * 2)       // 100352 bytes

__device__ __forceinline__ void gemm_prefetch(
    uint32_t smbase, int stage, int k0, int tid,
    const bf16* Ahg, const bf16* Alg, size_t a_stride, int m0,
    const bf16* Bhg, const bf16* Blg, size_t b_stride, int n0)
{
    uint32_t base = smbase + stage * (STAGE_E * 2);
    #pragma unroll
    for (int i = 0; i < 8; i++) {
        int lin = tid + i * 256;
        int pl = lin >> 10, rem = lin & 1023, r = rem >> 2, c4 = rem & 3;
        const bf16* srcp = (pl ? Alg : Ahg) + (size_t)(m0 + r) * a_stride + k0 + c4 * 8;
        cpa16(base + (pl * AB + r * ASTR + c4 * 8) * 2, srcp);
    }
    #pragma unroll
    for (int i = 0; i < 2; i++) {
        int lin = tid + i * 256;
        int pl = lin >> 8, rem = lin & 255, r = rem >> 3, c8 = rem & 7;
        const bf16* srcp = (pl ? Blg : Bhg) + (size_t)(k0 + r) * b_stride + n0 + c8 * 8;
        cpa16(base + (2 * AB + pl * BBE + r * BSTR + c8 * 8) * 2, srcp);
    }
    CPA_COMMIT();
}

__global__ __launch_bounds__(256, 2) void proj_cp(
    const float* __restrict__ bq, const float* __restrict__ bk,
    const float* __restrict__ bv)
{
    extern __shared__ bf16 sm[];
    const uint32_t smb = s2u(sm);
    const int tid = threadIdx.x, w = tid >> 5, lane = tid & 31;
    const int h = blockIdx.x, m0 = blockIdx.y * 256, z = blockIdx.z;
    const bf16* Xh = g_xh[z];
    const bf16* Xl = g_xl[z];
    const bf16* Wph = g_wh[z] + (size_t)h * D_ * DK;
    const bf16* Wpl = g_wl[z] + (size_t)h * D_ * DK;
    const float* bias = (z == 0) ? bq : (z == 1) ? bk : bv;
    bf16* outh = (z == 0) ? g_qh : (z == 1) ? g_kh : g_vh;
    bf16* outl = (z == 0) ? g_ql : (z == 1) ? g_kl : g_vl;
    const int m_off = (w & 3) * 64, n_off = (w >> 2) * 32;
    float acc[4][4][4] = {};

    gemm_prefetch(smb, 0, 0, tid, Xh, Xl, D_, m0, Wph, Wpl, DK, 0);
    gemm_prefetch(smb, 1, 32, tid, Xh, Xl, D_, m0, Wph, Wpl, DK, 0);
    for (int c = 0; c < 32; c++) {
        if (c < 31) { CPA_WAIT(1); } else { CPA_WAIT(0); }
        __syncthreads();
        bf16* Ah = sm + (c & 1) * STAGE_E;
        warp_chunk(Ah, Ah + AB, Ah + 2 * AB, Ah + 2 * AB + BBE, m_off, n_off, lane, acc);
        __syncthreads();
        if (c + 2 < 32)
            gemm_prefetch(smb, c & 1, (c + 2) * 32, tid, Xh, Xl, D_, m0, Wph, Wpl, DK, 0);
    }

    const int g = lane >> 2, q = lane & 3;
    #pragma unroll
    for (int mi = 0; mi < 4; mi++) {
        int m = m0 + m_off + mi * 16 + g;
        int b = m >> 10, s = m & 1023;
        size_t base0 = (((size_t)(b * H_ + h)) * S_ + s) * DK;
        size_t base1 = (((size_t)(b * H_ + h)) * S_ + s + 8) * DK;
        #pragma unroll
        for (int nj = 0; nj < 4; nj++) {
            int col = n_off + nj * 8 + q * 2;
            float bb0 = bias[h * DK + col], bb1 = bias[h * DK + col + 1];
            float v0 = acc[mi][nj][0] + bb0, v1 = acc[mi][nj][1] + bb1;
            float v2 = acc[mi][nj][2] + bb0, v3 = acc[mi][nj][3] + bb1;
            uint32_t hp0 = packbf(v0, v1), hp1 = packbf(v2, v3);
            float h0 = __uint_as_float(hp0 << 16), h1 = __uint_as_float(hp0 & 0xffff0000u);
            float h2 = __uint_as_float(hp1 << 16), h3 = __uint_as_float(hp1 & 0xffff0000u);
            uint32_t lp0 = packbf(v0 - h0, v1 - h1), lp1 = packbf(v2 - h2, v3 - h3);
            *(uint32_t*)&outh[base0 + col] = hp0;
            *(uint32_t*)&outl[base0 + col] = lp0;
            *(uint32_t*)&outh[base1 + col] = hp1;
            *(uint32_t*)&outl[base1 + col] = lp1;
        }
    }
}

// ===========================================================================
// outproj: out[m,n] = sum_k ctx_planes[m,k] Wo[k,n] + bo[n]
// grid (D_/64, MROWS/256), block 256, cp.async double-buffered
// ===========================================================================
__device__ __forceinline__ void outproj_prefetch(
    uint32_t smbase, int stage, int k0, int tid, int m0, int n0)
{
    uint32_t base = smbase + stage * (STAGE_E * 2);
    const int h = k0 >> 6, j0 = k0 & 63;
    #pragma unroll
    for (int i = 0; i < 8; i++) {
        int lin = tid + i * 256;
        int pl = lin >> 10, rem = lin & 1023, r = rem >> 2, c4 = rem & 3;
        int m = m0 + r;
        int b = m >> 10, s = m & 1023;
        const bf16* srcp = (pl ? g_cl : g_ch) +
            (((size_t)b * H_ + h) * S_ + s) * DK + j0 + c4 * 8;
        cpa16(base + (pl * AB + r * ASTR + c4 * 8) * 2, srcp);
    }
    #pragma unroll
    for (int i = 0; i < 2; i++) {
        int lin = tid + i * 256;
        int pl = lin >> 8, rem = lin & 255, r = rem >> 3, c8 = rem & 7;
        const bf16* srcp = (pl ? g_wol : g_woh) + (size_t)(k0 + r) * D_ + n0 + c8 * 8;
        cpa16(base + (2 * AB + pl * BBE + r * BSTR + c8 * 8) * 2, srcp);
    }
    CPA_COMMIT();
}

__global__ __launch_bounds__(256, 2) void outproj_cp(
    const float* __restrict__ bo, float* __restrict__ out)
{
    extern __shared__ bf16 sm[];
    const uint32_t smb = s2u(sm);
    const int tid = threadIdx.x, w = tid >> 5, lane = tid & 31;
    const int n0 = blockIdx.x * 64, m0 = blockIdx.y * 256;
    const int m_off = (w & 3) * 64, n_off = (w >> 2) * 32;
    float acc[4][4][4] = {};

    outproj_prefetch(smb, 0, 0, tid, m0, n0);
    outproj_prefetch(smb, 1, 32, tid, m0, n0);
    for (int c = 0; c < 32; c++) {
        if (c < 31) { CPA_WAIT(1); } else { CPA_WAIT(0); }
        __syncthreads();
        bf16* Ah = sm + (c & 1) * STAGE_E;
        warp_chunk(Ah, Ah + AB, Ah + 2 * AB, Ah + 2 * AB + BBE, m_off, n_off, lane, acc);
        __syncthreads();
        if (c + 2 < 32)
            outproj_prefetch(smb, c & 1, (c + 2) * 32, tid, m0, n0);
    }

    const int g = lane >> 2, q = lane & 3;
    #pragma unroll
    for (int mi = 0; mi < 4; mi++) {
        int m = m0 + m_off + mi * 16 + g;
        float* d0 = out + (size_t)m * D_ + n0;
        float* d1 = out + (size_t)(m + 8) * D_ + n0;
        #pragma unroll
        for (int nj = 0; nj < 4; nj++) {
            int col = n_off + nj * 8 + q * 2;
            float bb0 = bo[n0 + col], bb1 = bo[n0 + col + 1];
            *(float2*)&d0[col] = make_float2(acc[mi][nj][0] + bb0, acc[mi][nj][1] + bb1);
            *(float2*)&d1[col] = make_float2(acc[mi][nj][2] + bb0, acc[mi][nj][3] + bb1);
        }
    }
}

// ===========================================================================
// Fused attention: QK^T/8 -> softmax -> attn (gmem) + ctx (bf16 planes)
// grid (S_/32, BH), block 256 (8 warps). Dynamic smem 215040 B.
// ===========================================================================
#define SC_STR 1032
#define SC_BYTES (32 * SC_STR * 4)
#define KBUF_OFF SC_BYTES
#define KPLANE 18432
#define KBUF_SZ (2 * KPLANE)
#define Q_OFF (KBUF_OFF + 2 * KBUF_SZ)
#define FUSED_SMEM (Q_OFF + 2 * 4608)

__device__ __forceinline__ void attn_prefetch(
    char* smem, int bufidx, const bf16* ph, const bf16* pl,
    size_t bhS, int t0, int tid)
{
    uint32_t buf = s2u(smem + KBUF_OFF + bufidx * KBUF_SZ);
    #pragma unroll
    for (int i = 0; i < 8; i++) {
        int cid = tid + i * 256;
        int plane = cid >> 10, rem = cid & 1023;
        int row = rem >> 3, c16 = rem & 7;
        const bf16* src = (plane ? pl : ph) + (bhS + t0 + row) * DK + c16 * 8;
        cpa16(buf + plane * KPLANE + row * 144 + c16 * 16, src);
    }
    CPA_COMMIT();
}

__global__ __launch_bounds__(256) void attn_fused(
    const bf16* __restrict__ qh, const bf16* __restrict__ ql,
    const bf16* __restrict__ kh, const bf16* __restrict__ kl,
    const bf16* __restrict__ vh, const bf16* __restrict__ vl,
    float* __restrict__ attn, bf16* __restrict__ ctxh, bf16* __restrict__ ctxl)
{
    extern __shared__ char smem[];
    float* sc = (float*)smem;
    bf16* QH = (bf16*)(smem + Q_OFF);
    bf16* QL = (bf16*)(smem + Q_OFF + 4608);

    const int tid = threadIdx.x, w = tid >> 5, lane = tid & 31;
    const int s0 = blockIdx.x * 32;
    const int bh = blockIdx.y;
    const size_t bhS = (size_t)bh * S_;
    const int wm = w & 1, wn = w >> 1;
    const int g = lane >> 2, q = lane & 3;

    // stage Q (32x64, hi+lo planes)
    #pragma unroll
    for (int i = 0; i < 2; i++) {
        int lin = tid + i * 256;
        int plane = lin >> 8;
        int rem = lin & 255;
        int row = rem >> 3;
        int c16 = rem & 7;
        const bf16* src = (plane ? ql : qh) + (bhS + s0 + row) * DK + c16 * 8;
        bf16* dstp = (plane ? QL : QH) + row * BSTR + c16 * 8;
        *(uint4*)dstp = *(const uint4*)src;
    }

    attn_prefetch(smem, 0, kh, kl, bhS, 0, tid);
    attn_prefetch(smem, 1, kh, kl, bhS, 128, tid);
    __syncthreads();

    uint32_t aqh[4][4], aql[4][4];
    #pragma unroll
    for (int k4 = 0; k4 < 4; k4++) {
        ldsm4(aqh[k4], s2u(QH + (wm * 16 + (lane & 15)) * BSTR + k4 * 16 + (lane >> 4) * 8));
        ldsm4(aql[k4], s2u(QL + (wm * 16 + (lane & 15)) * BSTR + k4 * 16 + (lane >> 4) * 8));
    }

    // QK^T loop
    for (int c = 0; c < 8; c++) {
        if (c < 7) { CPA_WAIT(1); } else { CPA_WAIT(0); }
        __syncthreads();

        bf16* KHb = (bf16*)(smem + KBUF_OFF + (c & 1) * KBUF_SZ);
        bf16* KLb = (bf16*)(smem + KBUF_OFF + (c & 1) * KBUF_SZ + KPLANE);
        float acc[4][4] = {};
        #pragma unroll
        for (int k4 = 0; k4 < 4; k4++) {
            uint32_t bh4[2][4], bl4[2][4];
            #pragma unroll
            for (int j = 0; j < 2; j++)
                ldsm4(bh4[j], s2u(KHb + (wn * 32 + j * 16 + (lane & 7) + ((lane >> 4) << 3)) * BSTR
                                  + k4 * 16 + ((lane >> 3) & 1) * 8));
            #pragma unroll
            for (int nj = 0; nj < 4; nj++)
                mmabf(acc[nj], aqh[k4], &bh4[nj >> 1][(nj & 1) * 2]);
            #pragma unroll
            for (int j = 0; j < 2; j++)
                ldsm4(bl4[j], s2u(KLb + (wn * 32 + j * 16 + (lane & 7) + ((lane >> 4) << 3)) * BSTR
                                  + k4 * 16 + ((lane >> 3) & 1) * 8));
            #pragma unroll
            for (int nj = 0; nj < 4; nj++)
                mmabf(acc[nj], aqh[k4], &bl4[nj >> 1][(nj & 1) * 2]);
            #pragma unroll
            for (int nj = 0; nj < 4; nj++)
                mmabf(acc[nj], aql[k4], &bh4[nj >> 1][(nj & 1) * 2]);
        }
        #pragma unroll
        for (int nj = 0; nj < 4; nj++) {
            int col = c * 128 + wn * 32 + nj * 8 + q * 2;
            *(float2*)&sc[(wm * 16 + g) * SC_STR + col] =
                make_float2(acc[nj][0] * 0.125f, acc[nj][1] * 0.125f);
            *(float2*)&sc[(wm * 16 + g + 8) * SC_STR + col] =
                make_float2(acc[nj][2] * 0.125f, acc[nj][3] * 0.125f);
        }
        __syncthreads();
        if (c + 2 < 8)
            attn_prefetch(smem, c & 1, kh, kl, bhS, (c + 2) * 128, tid);
    }

    // V0 + V1 prefetch overlap softmax
    attn_prefetch(smem, 0, vh, vl, bhS, 0, tid);
    attn_prefetch(smem, 1, vh, vl, bhS, 128, tid);

    // softmax
    #pragma unroll
    for (int rr = 0; rr < 4; rr++) {
        const int row = w * 4 + rr;
        float* prow = sc + row * SC_STR;
        float4 v[8];
        float mx = -1e30f;
        #pragma unroll
        for (int j = 0; j < 8; j++) {
            v[j] = *(const float4*)&prow[lane * 4 + j * 128];
            mx = fmaxf(mx, fmaxf(fmaxf(v[j].x, v[j].y), fmaxf(v[j].z, v[j].w)));
        }
        #pragma unroll
        for (int off = 16; off > 0; off >>= 1)
            mx = fmaxf(mx, __shfl_xor_sync(0xffffffffu, mx, off));
        float sum = 0.f;
        #pragma unroll
        for (int j = 0; j < 8; j++) {
            v[j].x = __expf(v[j].x - mx); v[j].y = __expf(v[j].y - mx);
            v[j].z = __expf(v[j].z - mx); v[j].w = __expf(v[j].w - mx);
            sum += (v[j].x + v[j].y) + (v[j].z + v[j].w);
        }
        #pragma unroll
        for (int off = 16; off > 0; off >>= 1)
            sum += __shfl_xor_sync(0xffffffffu, sum, off);
        const float inv = 1.0f / sum;
        float* grow = attn + (bhS + s0 + row) * S_;
        #pragma unroll
        for (int j = 0; j < 8; j++) {
            float4 o = make_float4(v[j].x * inv, v[j].y * inv, v[j].z * inv, v[j].w * inv);
            *(float4*)&prow[lane * 4 + j * 128] = o;
            *(float4*)&grow[lane * 4 + j * 128] = o;
        }
    }
    __syncthreads();

    // ctx loop
    float acc2[2][4] = {};
    for (int c = 0; c < 8; c++) {
        if (c < 7) { CPA_WAIT(1); } else { CPA_WAIT(0); }
        __syncthreads();

        bf16* VHb = (bf16*)(smem + KBUF_OFF + (c & 1) * KBUF_SZ);
        bf16* VLb = (bf16*)(smem + KBUF_OFF + (c & 1) * KBUF_SZ + KPLANE);
        #pragma unroll
        for (int k4 = 0; k4 < 8; k4++) {
            int colb = c * 128 + k4 * 16 + q * 2;
            float2 x0 = *(const float2*)&sc[(wm * 16 + g) * SC_STR + colb];
            float2 x1 = *(const float2*)&sc[(wm * 16 + g + 8) * SC_STR + colb];
            float2 x2 = *(const float2*)&sc[(wm * 16 + g) * SC_STR + colb + 8];
            float2 x3 = *(const float2*)&sc[(wm * 16 + g + 8) * SC_STR + colb + 8];
            uint32_t ah[4], al[4];
            ah[0] = packbf(x0.x, x0.y); ah[1] = packbf(x1.x, x1.y);
            ah[2] = packbf(x2.x, x2.y); ah[3] = packbf(x3.x, x3.y);
            al[0] = packbf(x0.x - __uint_as_float(ah[0] << 16), x0.y - __uint_as_float(ah[0] & 0xffff0000u));
            al[1] = packbf(x1.x - __uint_as_float(ah[1] << 16), x1.y - __uint_as_float(ah[1] & 0xffff0000u));
            al[2] = packbf(x2.x - __uint_as_float(ah[2] << 16), x2.y - __uint_as_float(ah[2] & 0xffff0000u));
            al[3] = packbf(x3.x - __uint_as_float(ah[3] << 16), x3.y - __uint_as_float(ah[3] & 0xffff0000u));

            uint32_t bhf[4], blf[4];
            ldsm4t(bhf, s2u(VHb + (k4 * 16 + (lane & 15)) * BSTR + wn * 16 + (lane >> 4) * 8));
            ldsm4t(blf, s2u(VLb + (k4 * 16 + (lane & 15)) * BSTR + wn * 16 + (lane >> 4) * 8));
            #pragma unroll
            for (int nj = 0; nj < 2; nj++) {
                mmabf(acc2[nj], ah, &bhf[nj * 2]);
                mmabf(acc2[nj], ah, &blf[nj * 2]);
                mmabf(acc2[nj], al, &bhf[nj * 2]);
            }
        }
        __syncthreads();
        if (c + 2 < 8)
            attn_prefetch(smem, c & 1, vh, vl, bhS, (c + 2) * 128, tid);
    }

    // ctx epilogue: write bf16 hi/lo planes
    #pragma unroll
    for (int nj = 0; nj < 2; nj++) {
        int col = wn * 16 + nj * 8 + q * 2;
        size_t i0 = (bhS + s0 + wm * 16 + g) * DK + col;
        size_t i1 = (bhS + s0 + wm * 16 + g + 8) * DK + col;
        uint32_t hp0 = packbf(acc2[nj][0], acc2[nj][1]);
        uint32_t hp1 = packbf(acc2[nj][2], acc2[nj][3]);
        float h0 = __uint_as_float(hp0 << 16), h1 = __uint_as_float(hp0 & 0xffff0000u);
        float h2 = __uint_as_float(hp1 << 16), h3 = __uint_as_float(hp1 & 0xffff0000u);
        uint32_t lp0 = packbf(acc2[nj][0] - h0, acc2[nj][1] - h1);
        uint32_t lp1 = packbf(acc2[nj][2] - h2, acc2[nj][3] - h3);
        *(uint32_t*)&ctxh[i0] = hp0;
        *(uint32_t*)&ctxl[i0] = lp0;
        *(uint32_t*)&ctxh[i1] = hp1;
        *(uint32_t*)&ctxl[i1] = lp1;
    }
}

// ---------------------------------------------------------------------------
extern "C" void kernel_launch(void* const* d_in, const int* in_sizes, int n_in,
                              void* d_out, int out_size)
{
    const float* query = (const float*)d_in[0];
    const float* key   = (const float*)d_in[1];
    const float* value = (const float*)d_in[2];
    const float* Wq    = (const float*)d_in[3];
    const float* bq    = (const float*)d_in[4];
    const float* Wk    = (const float*)d_in[5];
    const float* bk    = (const float*)d_in[6];
    const float* Wv    = (const float*)d_in[7];
    const float* bv    = (const float*)d_in[8];
    const float* Wo    = (const float*)d_in[9];
    const float* bo    = (const float*)d_in[10];
    float* out = (float*)d_out;

    bf16 *xh, *xl, *wh, *wl, *woh, *wol;
    bf16 *qh, *ql, *kh, *kl, *vh, *vl, *ch, *cl;
    float *attn_scratch;
    cudaGetSymbolAddress((void**)&xh, g_xh);
    cudaGetSymbolAddress((void**)&xl, g_xl);
    cudaGetSymbolAddress((void**)&wh, g_wh);
    cudaGetSymbolAddress((void**)&wl, g_wl);
    cudaGetSymbolAddress((void**)&woh, g_woh);
    cudaGetSymbolAddress((void**)&wol, g_wol);
    cudaGetSymbolAddress((void**)&qh, g_qh);
    cudaGetSymbolAddress((void**)&ql, g_ql);
    cudaGetSymbolAddress((void**)&kh, g_kh);
    cudaGetSymbolAddress((void**)&kl, g_kl);
    cudaGetSymbolAddress((void**)&vh, g_vh);
    cudaGetSymbolAddress((void**)&vl, g_vl);
    cudaGetSymbolAddress((void**)&ch, g_ch);
    cudaGetSymbolAddress((void**)&cl, g_cl);
    cudaGetSymbolAddress((void**)&attn_scratch, g_attn);

    const size_t out_elems  = (size_t)B_ * S_ * D_;
    const size_t attn_elems = (size_t)BH * S_ * S_;
    float* attn = ((size_t)out_size >= out_elems + attn_elems)
                      ? (out + out_elems) : attn_scratch;

    static int smem_set = 0;
    if (!smem_set) {
        cudaFuncSetAttribute(proj_cp, cudaFuncAttributeMaxDynamicSharedMemorySize, SMEM_PJ);
        cudaFuncSetAttribute(outproj_cp, cudaFuncAttributeMaxDynamicSharedMemorySize, SMEM_PJ);
        cudaFuncSetAttribute(attn_fused, cudaFuncAttributeMaxDynamicSharedMemorySize, FUSED_SMEM);
        smem_set = 1;
    }

    const size_t XN = (size_t)MROWS * D_;   // 8388608
    const size_t WN = (size_t)H_ * D_ * DK; // 1048576

    // convert inputs to bf16 hi/lo planes
    cvt_kernel<<<XN / 1024, 256>>>(query, xh + 0 * XN, xl + 0 * XN, (int)XN);
    cvt_kernel<<<XN / 1024, 256>>>(key,   xh + 1 * XN, xl + 1 * XN, (int)XN);
    cvt_kernel<<<XN / 1024, 256>>>(value, xh + 2 * XN, xl + 2 * XN, (int)XN);
    cvt_kernel<<<WN / 1024, 256>>>(Wq, wh + 0 * WN, wl + 0 * WN, (int)WN);
    cvt_kernel<<<WN / 1024, 256>>>(Wk, wh + 1 * WN, wl + 1 * WN, (int)WN);
    cvt_kernel<<<WN / 1024, 256>>>(Wv, wh + 2 * WN, wl + 2 * WN, (int)WN);
    cvt_kernel<<<WN / 1024, 256>>>(Wo, woh, wol, (int)WN);

    proj_cp<<<dim3(H_, MROWS / 256, 3), 256, SMEM_PJ>>>(bq, bk, bv);
    attn_fused<<<dim3(S_ / 32, BH), 256, FUSED_SMEM>>>(qh, ql, kh, kl, vh, vl, attn, ch, cl);
    outproj_cp<<<dim3(D_ / 64, MROWS / 256), 256, SMEM_PJ>>>(bo, out);
}